// round 8
// baseline (speedup 1.0000x reference)
#include <cuda_runtime.h>
#include <math.h>

#define BATCH 8
#define M0 228000
#define M1 57000
#define KSEL 2000
#define CAND 4000
#define POSTK 1000
#define IMG_Wf 1216.0f
#define IMG_Hf 800.0f
#define LVL_OFF 1217.0f
#define SCALE_CLAMPF 4.135166556742356f
#define NMS_T 0.7f
#define NWORD 125            /* 4000/32 */
#define MROW  128            /* padded words per mask row (512B = 32 uint4) */
#define MROW4 32             /* uint4 per mask row */
#define RING  80             /* ring slots: 80*512B = 40KB */
#define NPROD 16             /* producer warps in scan kernel */

// ---------------- scratch (device globals; no allocation allowed) ----------
__device__ int      g_cand[BATCH * CAND];
__device__ float4   g_sbox[BATCH * CAND];
__device__ float4   g_snb [BATCH * CAND];
__device__ float    g_sarea[BATCH * CAND];
__device__ float    g_sscore[BATCH * CAND];
__device__ int      g_slvl[BATCH * CAND];
__device__ uint4    g_mask4[(size_t)BATCH * CAND * MROW4];   // 16 MB

__device__ __forceinline__ unsigned fkey(float f) {
    unsigned u = __float_as_uint(f);
    return (u & 0x80000000u) ? ~u : (u | 0x80000000u);
}
__device__ __forceinline__ float fkey_inv(unsigned u) {
    return (u & 0x80000000u) ? __uint_as_float(u & 0x7fffffffu)
                             : __uint_as_float(~u);
}

// ---------------- K1: exact top-K SET per (image, level) -------------------
// Per-warp histograms + match_any aggregation. All warp collectives run on
// PADDED iteration counts so every thread participates in every trip.
__global__ void topk_kernel(const float* __restrict__ lg0,
                            const float* __restrict__ lg1) {
    int blk = blockIdx.x;
    int b = blk >> 1, lvl = blk & 1;
    const float* lg = lvl ? (lg1 + (size_t)b * M1) : (lg0 + (size_t)b * M0);
    int M = lvl ? M1 : M0;
    int t = threadIdx.x;
    int lane = t & 31, warp = t >> 5;

    __shared__ unsigned hist[32][256];      // 32 KB
    __shared__ unsigned tot[256];
    __shared__ unsigned sh_prefix;
    __shared__ int      sh_kRem, sh_cnt, sh_nTie;
    __shared__ int      tieBuf[512];

    if (t == 0) { sh_prefix = 0u; sh_kRem = KSEL; sh_cnt = 0; sh_nTie = 0; }
    __syncthreads();

    const float4* lg4 = (const float4*)lg;
    int M4 = M >> 2;
    int iters = (M4 + 1023) >> 10;          // padded trip count

    for (int shift = 24; shift >= 0; shift -= 8) {
        for (int i = t; i < 32 * 256; i += 1024) ((unsigned*)hist)[i] = 0u;
        __syncthreads();
        unsigned prefix = sh_prefix;
        unsigned pmask  = (shift == 24) ? 0u : ~((1u << (shift + 8)) - 1u);
        for (int it = 0; it < iters; ++it) {
            int i = it * 1024 + t;
            bool inb = (i < M4);
            float4 v = inb ? lg4[i] : make_float4(0.f, 0.f, 0.f, 0.f);
            unsigned uu[4] = { fkey(v.x), fkey(v.y), fkey(v.z), fkey(v.w) };
            #pragma unroll
            for (int c = 0; c < 4; ++c) {
                bool take = inb && ((uu[c] & pmask) == prefix);
                unsigned bin = (uu[c] >> shift) & 255u;
                unsigned active = __ballot_sync(0xffffffffu, take);
                if (take) {
                    unsigned peers = __match_any_sync(active, bin);
                    int leader = __ffs(peers) - 1;
                    if (lane == leader)
                        atomicAdd(&hist[warp][bin], __popc(peers));
                }
            }
        }
        __syncthreads();
        if (t < 256) {
            unsigned s = 0;
            #pragma unroll
            for (int w = 0; w < 32; ++w) s += hist[w][t];
            tot[t] = s;
        }
        __syncthreads();
        if (t == 0) {
            int kr = sh_kRem, cum = 0, bsel = 0;
            for (int bin = 255; bin >= 0; --bin) {
                int c = (int)tot[bin];
                if (cum + c >= kr) { bsel = bin; sh_kRem = kr - cum; break; }
                cum += c;
            }
            sh_prefix = prefix | ((unsigned)bsel << shift);
        }
        __syncthreads();
    }
    unsigned T = sh_prefix;

    // compaction: per-thread atomics only (safe with early loop exit)
    int base = b * CAND + lvl * KSEL;
    for (int i4 = t; i4 < M4; i4 += 1024) {
        float4 v = lg4[i4];
        int i = i4 * 4;
        unsigned uu[4] = { fkey(v.x), fkey(v.y), fkey(v.z), fkey(v.w) };
        #pragma unroll
        for (int c = 0; c < 4; ++c) {
            unsigned u = uu[c];
            if (u > T) {
                int sl = atomicAdd(&sh_cnt, 1);
                g_cand[base + sl] = (lvl << 18) | (i + c);
            } else if (u == T) {
                int sl = atomicAdd(&sh_nTie, 1);
                if (sl < 512) tieBuf[sl] = i + c;
            }
        }
    }
    __syncthreads();
    if (t == 0) {
        int n = sh_nTie < 512 ? sh_nTie : 512;
        int need = KSEL - sh_cnt;
        for (int a = 0; a < need && a < n; ++a) {
            int best = a;
            for (int c = a + 1; c < n; ++c)
                if (tieBuf[c] < tieBuf[best]) best = c;
            int tmp = tieBuf[a]; tieBuf[a] = tieBuf[best]; tieBuf[best] = tmp;
            g_cand[base + sh_cnt + a] = (lvl << 18) | tieBuf[a];
        }
    }
}

// ---------------- K2: per-image sort + decode ------------------------------
__global__ void sortdecode_kernel(const float* __restrict__ lg0, const float* __restrict__ dl0,
                                  const float* __restrict__ lg1, const float* __restrict__ dl1,
                                  const float* __restrict__ an0, const float* __restrict__ an1) {
    int b = blockIdx.x, t = threadIdx.x;
    __shared__ unsigned long long key[4096];

    for (int i = t; i < 4096; i += 1024) {
        if (i < CAND) {
            int p = g_cand[b * CAND + i];
            int lvl = p >> 18, idx = p & 0x3ffff;
            float sc = lvl ? lg1[(size_t)b * M1 + idx] : lg0[(size_t)b * M0 + idx];
            key[i] = ((unsigned long long)fkey(sc) << 32) | (unsigned)(~(unsigned)p);
        } else key[i] = 0ull;
    }
    __syncthreads();

    // bitonic sort, descending: (score desc, lvl asc, idx asc) = concat order
    for (int k = 2; k <= 4096; k <<= 1) {
        for (int j = k >> 1; j > 0; j >>= 1) {
            for (int e = t; e < 4096; e += 1024) {
                int ix = e ^ j;
                if (ix > e) {
                    unsigned long long a = key[e], bb = key[ix];
                    bool swp = ((e & k) == 0) ? (a < bb) : (a > bb);
                    if (swp) { key[e] = bb; key[ix] = a; }
                }
            }
            __syncthreads();
        }
    }

    for (int i = t; i < CAND; i += 1024) {
        unsigned long long k = key[i];
        unsigned p = ~((unsigned)k);
        int lvl = (int)(p >> 18), idx = (int)(p & 0x3ffffu);
        float score = fkey_inv((unsigned)(k >> 32));

        const float* dl = lvl ? (dl1 + ((size_t)b * M1 + idx) * 4)
                              : (dl0 + ((size_t)b * M0 + idx) * 4);
        const float* an = (lvl ? an1 : an0) + (size_t)idx * 4;
        float4 a = *(const float4*)an;
        float4 d = *(const float4*)dl;

        float w  = __fsub_rn(a.z, a.x);
        float h  = __fsub_rn(a.w, a.y);
        float cx = __fadd_rn(a.x, __fmul_rn(0.5f, w));
        float cy = __fadd_rn(a.y, __fmul_rn(0.5f, h));
        float dw = fminf(d.z, SCALE_CLAMPF);
        float dh = fminf(d.w, SCALE_CLAMPF);
        float pcx = __fadd_rn(__fmul_rn(d.x, w), cx);
        float pcy = __fadd_rn(__fmul_rn(d.y, h), cy);
        float pw  = __fmul_rn(expf(dw), w);
        float ph  = __fmul_rn(expf(dh), h);
        float hpw = __fmul_rn(0.5f, pw);
        float hph = __fmul_rn(0.5f, ph);
        float x1 = __fsub_rn(pcx, hpw);
        float y1 = __fsub_rn(pcy, hph);
        float x2 = __fadd_rn(pcx, hpw);
        float y2 = __fadd_rn(pcy, hph);
        x1 = fminf(fmaxf(x1, 0.f), IMG_Wf);
        x2 = fminf(fmaxf(x2, 0.f), IMG_Wf);
        y1 = fminf(fmaxf(y1, 0.f), IMG_Hf);
        y2 = fminf(fmaxf(y2, 0.f), IMG_Hf);

        int gi = b * CAND + i;
        g_sbox[gi] = make_float4(x1, y1, x2, y2);
        float off = lvl ? LVL_OFF : 0.f;
        float nx1 = __fadd_rn(x1, off), ny1 = __fadd_rn(y1, off);
        float nx2 = __fadd_rn(x2, off), ny2 = __fadd_rn(y2, off);
        g_snb[gi]   = make_float4(nx1, ny1, nx2, ny2);
        g_sarea[gi] = __fmul_rn(__fsub_rn(nx2, nx1), __fsub_rn(ny2, ny1));
        g_sscore[gi] = score;
        g_slvl[gi]  = lvl;
    }
}

// ---------------- K3: 4000x4000 suppression bitmask per image --------------
__global__ void mask_kernel() {
    int blk = blockIdx.x;
    int b = blk / 250, rg = blk % 250;
    int t = threadIdx.x, wi = t >> 5, lane = t & 31;
    unsigned* gm = (unsigned*)g_mask4;

    for (int rr = 0; rr < 2; ++rr) {
        int row = rg * 16 + wi * 2 + rr;
        int gr = b * CAND + row;
        float4 jb = g_snb[gr];
        float  ja = g_sarea[gr];
        unsigned* mrow = gm + (size_t)gr * MROW;
        for (int w = 0; w < NWORD; ++w) {
            int col = b * CAND + w * 32 + lane;
            float4 nb = g_snb[col];
            float  na = g_sarea[col];
            float ix1 = fmaxf(jb.x, nb.x), iy1 = fmaxf(jb.y, nb.y);
            float ix2 = fminf(jb.z, nb.z), iy2 = fminf(jb.w, nb.w);
            float iw = fmaxf(__fsub_rn(ix2, ix1), 0.f);
            float ih = fmaxf(__fsub_rn(iy2, iy1), 0.f);
            float inter = __fmul_rn(iw, ih);
            float denom = fmaxf(__fsub_rn(__fadd_rn(ja, na), inter), 1e-6f);
            float iou = __fdiv_rn(inter, denom);
            unsigned bits = __ballot_sync(0xffffffffu, iou > NMS_T);
            if (lane == 0) mrow[w] = bits;
        }
    }
}

// ---------------- K4: serial sorted scan; 16 producer warps + 1 consumer ---
__global__ void scan_kernel(float* __restrict__ out) {
    int b = blockIdx.x;
    int t = threadIdx.x, warp = t >> 5, lane = t & 31;
    __shared__ volatile int sh_cons;        // consumer scan position (monotone)
    __shared__ volatile int sh_done;
    __shared__ volatile int flags[RING];    // slot -> row+1 when published
    __shared__ uint4 ring[RING * MROW4];    // 40 KB

    if (t == 0) { sh_cons = 0; sh_done = 0; }
    for (int i = t; i < RING; i += blockDim.x) flags[i] = 0;
    __syncthreads();

    const uint4* mbase = g_mask4 + (size_t)b * CAND * MROW4;

    if (warp >= 1) {
        // -------- producers: warp p handles rows p-1, p-1+NPROD, ... --------
        for (int r = warp - 1; r < CAND; r += NPROD) {
            int stop = 0;
            if (lane == 0) {
                while (r >= sh_cons + RING && !sh_done) {}
                if (sh_done) stop = 1;
            }
            stop = __shfl_sync(0xffffffffu, stop, 0);
            if (stop) break;
            ring[(r % RING) * MROW4 + lane] = mbase[(size_t)r * MROW4 + lane];
            __threadfence_block();
            __syncwarp();
            if (lane == 0) flags[r % RING] = r + 1;
        }
    } else {
        // -------- consumer: register-resident 4000-bit suppressed mask ------
        unsigned m0 = 0, m1 = 0, m2 = 0, m3 = 0;   // lane L owns words 4L..4L+3

        int sel = 0;
        for (int w = 0; w < NWORD && sel < POSTK; ++w) {
            if (lane == 0) sh_cons = w * 32;
            unsigned v = (w & 3) == 0 ? m0 : (w & 3) == 1 ? m1 : (w & 3) == 2 ? m2 : m3;
            unsigned cur = __shfl_sync(0xffffffffu, v, w >> 2);
            unsigned alive = ~cur;
            while (alive && sel < POSTK) {
                int bit = __ffs(alive) - 1;
                int i = w * 32 + bit;
                if (lane == 0) { while (flags[i % RING] != i + 1) {} }
                __syncwarp();
                const volatile unsigned* rr =
                    (const volatile unsigned*)(ring + (i % RING) * MROW4) + lane * 4;
                m0 |= rr[0]; m1 |= rr[1]; m2 |= rr[2]; m3 |= rr[3];
                if (lane == 0) {
                    float4 bx = g_sbox[b * CAND + i];
                    float scv = g_sscore[b * CAND + i];
                    float* o = out + ((size_t)b * POSTK + sel) * 5;
                    o[0] = bx.x; o[1] = bx.y; o[2] = bx.z; o[3] = bx.w; o[4] = scv;
                }
                sel++;
                unsigned v2 = (w & 3) == 0 ? m0 : (w & 3) == 1 ? m1 : (w & 3) == 2 ? m2 : m3;
                unsigned curw = __shfl_sync(0xffffffffu, v2, w >> 2);
                alive &= ~curw;
                alive &= ~(1u << bit);
            }
        }
        if (lane == 0) sh_done = 1;
        __threadfence_block();

        // pad remaining rows with concat-position-0 candidate (first lvl-0)
        if (sel < POSTK) {
            int padi = -1;
            for (int base = 0; padi < 0; base += 32) {
                int ok = (g_slvl[b * CAND + base + lane] == 0);
                unsigned mm = __ballot_sync(0xffffffffu, ok);
                if (mm) padi = base + __ffs(mm) - 1;
            }
            float4 padBox  = g_sbox[b * CAND + padi];
            float padScore = g_sscore[b * CAND + padi];
            for (int r = sel + lane; r < POSTK; r += 32) {
                float* o = out + ((size_t)b * POSTK + r) * 5;
                o[0] = padBox.x; o[1] = padBox.y; o[2] = padBox.z; o[3] = padBox.w;
                o[4] = padScore;
            }
        }
    }
}

// ---------------------------------------------------------------------------
extern "C" void kernel_launch(void* const* d_in, const int* in_sizes, int n_in,
                              void* d_out, int out_size) {
    const float* lg0 = (const float*)d_in[0];
    const float* dl0 = (const float*)d_in[1];
    const float* lg1 = (const float*)d_in[2];
    const float* dl1 = (const float*)d_in[3];
    const float* an0 = (const float*)d_in[4];
    const float* an1 = (const float*)d_in[5];
    float* out = (float*)d_out;

    topk_kernel<<<BATCH * 2, 1024>>>(lg0, lg1);
    sortdecode_kernel<<<BATCH, 1024>>>(lg0, dl0, lg1, dl1, an0, an1);
    mask_kernel<<<BATCH * 250, 256>>>();
    scan_kernel<<<BATCH, (NPROD + 1) * 32>>>(out);
}

// round 9
// speedup vs baseline: 1.1216x; 1.1216x over previous
#include <cuda_runtime.h>
#include <math.h>

#define BATCH 8
#define M0 228000
#define M1 57000
#define KSEL 2000
#define CAND 4000
#define POSTK 1000
#define IMG_Wf 1216.0f
#define IMG_Hf 800.0f
#define LVL_OFF 1217.0f
#define SCALE_CLAMPF 4.135166556742356f
#define NMS_T 0.7f
#define NWORD 125            /* 4000/32 */
#define MROW  128            /* padded words per mask row (512B = 32 uint4) */
#define MROW4 32             /* uint4 per mask row */
#define RING  256            /* ring slots: 256*512B = 128KB */
#define NPROD 31             /* producer warps (block = 1024 thr) */
#define NUNITS 16            /* BATCH * 2 levels */
#define NB16 65536
#define HSLICE 14
#define TIECAP 4096

/* scan kernel dynamic smem: ring + flags + sup + selList + ctrl */
#define SCAN_SMEM (RING * 512 + (RING + 128 + 1024 + 16) * 4)

// ---------------- scratch (device globals; no allocation allowed) ----------
__device__ unsigned g_hist[NUNITS * NB16];            // 4 MB
__device__ int      g_cand[BATCH * CAND];
__device__ float4   g_sbox[BATCH * CAND];
__device__ float4   g_snb [BATCH * CAND];
__device__ float    g_sarea[BATCH * CAND];
__device__ float    g_sscore[BATCH * CAND];
__device__ int      g_slvl[BATCH * CAND];
__device__ uint4    g_mask4[(size_t)BATCH * CAND * MROW4];   // 16 MB

__device__ __forceinline__ unsigned fkey(float f) {
    unsigned u = __float_as_uint(f);
    return (u & 0x80000000u) ? ~u : (u | 0x80000000u);
}
__device__ __forceinline__ float fkey_inv(unsigned u) {
    return (u & 0x80000000u) ? __uint_as_float(u & 0x7fffffffu)
                             : __uint_as_float(~u);
}

// ---------------- K0a: zero the 16-bit histograms --------------------------
__global__ void zero_kernel() {
    int i = blockIdx.x * 1024 + threadIdx.x;
    if (i < NUNITS * NB16) g_hist[i] = 0u;
}

// ---------------- K0b: chip-wide 16-bit histogram per (image, level) -------
__global__ void hist_kernel(const float* __restrict__ lg0,
                            const float* __restrict__ lg1) {
    int unit = blockIdx.x / HSLICE;
    int slice = blockIdx.x % HSLICE;
    int b = unit >> 1, lvl = unit & 1;
    const float* lg = lvl ? (lg1 + (size_t)b * M1) : (lg0 + (size_t)b * M0);
    int M4 = (lvl ? M1 : M0) >> 2;
    const float4* lg4 = (const float4*)lg;
    unsigned* H = g_hist + unit * NB16;

    int chunk = (M4 + HSLICE - 1) / HSLICE;
    int s = slice * chunk;
    int e = s + chunk; if (e > M4) e = M4;
    for (int i = s + threadIdx.x; i < e; i += 1024) {
        float4 v = lg4[i];
        atomicAdd(&H[fkey(v.x) >> 16], 1u);
        atomicAdd(&H[fkey(v.y) >> 16], 1u);
        atomicAdd(&H[fkey(v.z) >> 16], 1u);
        atomicAdd(&H[fkey(v.w) >> 16], 1u);
    }
}

// ---------------- K1: threshold + tie-rank + compaction per unit -----------
__global__ void thresh_kernel(const float* __restrict__ lg0,
                              const float* __restrict__ lg1) {
    int unit = blockIdx.x;
    int b = unit >> 1, lvl = unit & 1;
    const float* lg = lvl ? (lg1 + (size_t)b * M1) : (lg0 + (size_t)b * M0);
    int M4 = (lvl ? M1 : M0) >> 2;
    const float4* lg4 = (const float4*)lg;
    const unsigned* H = g_hist + unit * NB16;
    int t = threadIdx.x;

    __shared__ unsigned chunkSum[1024];
    __shared__ int sh_chunk, sh_nBefore, sh_T16, sh_ngt, sh_cnt, sh_nTie;
    __shared__ unsigned long long tieKey[TIECAP];   // 32 KB

    // phase A: per-thread 64-bin chunk sums, then find threshold bin
    unsigned s = 0;
    #pragma unroll 8
    for (int j = 0; j < 64; ++j) s += H[t * 64 + j];
    chunkSum[t] = s;
    if (t == 0) { sh_cnt = 0; sh_nTie = 0; }
    __syncthreads();
    if (t == 0) {
        unsigned cum = 0;
        for (int tt = 1023; tt >= 0; --tt) {
            if (cum + chunkSum[tt] >= KSEL) { sh_chunk = tt; sh_nBefore = (int)cum; break; }
            cum += chunkSum[tt];
        }
    }
    __syncthreads();
    if (t == sh_chunk) {
        unsigned cum = (unsigned)sh_nBefore;
        for (int j = 63; j >= 0; --j) {
            unsigned c = H[t * 64 + j];
            if (cum + c >= KSEL) { sh_T16 = t * 64 + j; sh_ngt = (int)cum; break; }
            cum += c;
        }
    }
    __syncthreads();
    unsigned T16 = (unsigned)sh_T16;
    int n_gt = sh_ngt;
    int kRem = KSEL - n_gt;
    int base = b * CAND + lvl * KSEL;

    // phase B: compaction (set only; order handled by sort kernel)
    for (int i4 = t; i4 < M4; i4 += 1024) {
        float4 v = lg4[i4];
        int i = i4 * 4;
        unsigned uu[4] = { fkey(v.x), fkey(v.y), fkey(v.z), fkey(v.w) };
        #pragma unroll
        for (int c = 0; c < 4; ++c) {
            unsigned h = uu[c] >> 16;
            if (h > T16) {
                int sl = atomicAdd(&sh_cnt, 1);
                g_cand[base + sl] = (lvl << 18) | (i + c);
            } else if (h == T16) {
                int sl = atomicAdd(&sh_nTie, 1);
                if (sl < TIECAP)
                    tieKey[sl] = ((unsigned long long)uu[c] << 32) |
                                 (unsigned)(~(unsigned)(i + c));
            }
        }
    }
    __syncthreads();

    // phase C: rank the ties (full key desc, idx asc); keep rank < kRem
    int n = sh_nTie < TIECAP ? sh_nTie : TIECAP;
    for (int e = t; e < n; e += 1024) {
        unsigned long long k = tieKey[e];
        int r = 0;
        for (int c = 0; c < n; ++c) r += (tieKey[c] > k);
        if (r < kRem) {
            int idx = (int)(~(unsigned)k);
            g_cand[base + n_gt + r] = (lvl << 18) | idx;
        }
    }
}

// ---------------- K2: per-image sort + decode ------------------------------
__global__ void sortdecode_kernel(const float* __restrict__ lg0, const float* __restrict__ dl0,
                                  const float* __restrict__ lg1, const float* __restrict__ dl1,
                                  const float* __restrict__ an0, const float* __restrict__ an1) {
    int b = blockIdx.x, t = threadIdx.x;
    __shared__ unsigned long long key[4096];

    for (int i = t; i < 4096; i += 1024) {
        if (i < CAND) {
            int p = g_cand[b * CAND + i];
            int lvl = p >> 18, idx = p & 0x3ffff;
            float sc = lvl ? lg1[(size_t)b * M1 + idx] : lg0[(size_t)b * M0 + idx];
            key[i] = ((unsigned long long)fkey(sc) << 32) | (unsigned)(~(unsigned)p);
        } else key[i] = 0ull;
    }
    __syncthreads();

    // bitonic sort, descending: (score desc, lvl asc, idx asc) = concat order
    for (int k = 2; k <= 4096; k <<= 1) {
        for (int j = k >> 1; j > 0; j >>= 1) {
            for (int e = t; e < 4096; e += 1024) {
                int ix = e ^ j;
                if (ix > e) {
                    unsigned long long a = key[e], bb = key[ix];
                    bool swp = ((e & k) == 0) ? (a < bb) : (a > bb);
                    if (swp) { key[e] = bb; key[ix] = a; }
                }
            }
            __syncthreads();
        }
    }

    for (int i = t; i < CAND; i += 1024) {
        unsigned long long k = key[i];
        unsigned p = ~((unsigned)k);
        int lvl = (int)(p >> 18), idx = (int)(p & 0x3ffffu);
        float score = fkey_inv((unsigned)(k >> 32));

        const float* dl = lvl ? (dl1 + ((size_t)b * M1 + idx) * 4)
                              : (dl0 + ((size_t)b * M0 + idx) * 4);
        const float* an = (lvl ? an1 : an0) + (size_t)idx * 4;
        float4 a = *(const float4*)an;
        float4 d = *(const float4*)dl;

        float w  = __fsub_rn(a.z, a.x);
        float h  = __fsub_rn(a.w, a.y);
        float cx = __fadd_rn(a.x, __fmul_rn(0.5f, w));
        float cy = __fadd_rn(a.y, __fmul_rn(0.5f, h));
        float dw = fminf(d.z, SCALE_CLAMPF);
        float dh = fminf(d.w, SCALE_CLAMPF);
        float pcx = __fadd_rn(__fmul_rn(d.x, w), cx);
        float pcy = __fadd_rn(__fmul_rn(d.y, h), cy);
        float pw  = __fmul_rn(expf(dw), w);
        float ph  = __fmul_rn(expf(dh), h);
        float hpw = __fmul_rn(0.5f, pw);
        float hph = __fmul_rn(0.5f, ph);
        float x1 = __fsub_rn(pcx, hpw);
        float y1 = __fsub_rn(pcy, hph);
        float x2 = __fadd_rn(pcx, hpw);
        float y2 = __fadd_rn(pcy, hph);
        x1 = fminf(fmaxf(x1, 0.f), IMG_Wf);
        x2 = fminf(fmaxf(x2, 0.f), IMG_Wf);
        y1 = fminf(fmaxf(y1, 0.f), IMG_Hf);
        y2 = fminf(fmaxf(y2, 0.f), IMG_Hf);

        int gi = b * CAND + i;
        g_sbox[gi] = make_float4(x1, y1, x2, y2);
        float off = lvl ? LVL_OFF : 0.f;
        float nx1 = __fadd_rn(x1, off), ny1 = __fadd_rn(y1, off);
        float nx2 = __fadd_rn(x2, off), ny2 = __fadd_rn(y2, off);
        g_snb[gi]   = make_float4(nx1, ny1, nx2, ny2);
        g_sarea[gi] = __fmul_rn(__fsub_rn(nx2, nx1), __fsub_rn(ny2, ny1));
        g_sscore[gi] = score;
        g_slvl[gi]  = lvl;
    }
}

// ---------------- K3: 4000x4000 suppression bitmask per image --------------
__global__ void mask_kernel() {
    int blk = blockIdx.x;
    int b = blk / 250, rg = blk % 250;
    int t = threadIdx.x, wi = t >> 5, lane = t & 31;
    unsigned* gm = (unsigned*)g_mask4;

    for (int rr = 0; rr < 2; ++rr) {
        int row = rg * 16 + wi * 2 + rr;
        int gr = b * CAND + row;
        float4 jb = g_snb[gr];
        float  ja = g_sarea[gr];
        unsigned* mrow = gm + (size_t)gr * MROW;
        for (int w = 0; w < NWORD; ++w) {
            int col = b * CAND + w * 32 + lane;
            float4 nb = g_snb[col];
            float  na = g_sarea[col];
            float ix1 = fmaxf(jb.x, nb.x), iy1 = fmaxf(jb.y, nb.y);
            float ix2 = fminf(jb.z, nb.z), iy2 = fminf(jb.w, nb.w);
            float iw = fmaxf(__fsub_rn(ix2, ix1), 0.f);
            float ih = fmaxf(__fsub_rn(iy2, iy1), 0.f);
            float inter = __fmul_rn(iw, ih);
            float denom = fmaxf(__fsub_rn(__fadd_rn(ja, na), inter), 1e-6f);
            float iou = __fdiv_rn(inter, denom);
            unsigned bits = __ballot_sync(0xffffffffu, iou > NMS_T);
            if (lane == 0) mrow[w] = bits;
        }
    }
}

// ---------------- K4: serial sorted scan; 31 producers + 1 consumer --------
// Output deferred to a parallel epilogue; consumer loop is pure smem/shfl.
__global__ void scan_kernel(float* __restrict__ out) {
    int b = blockIdx.x;
    int t = threadIdx.x, warp = t >> 5, lane = t & 31;

    extern __shared__ uint4 sdyn4[];
    uint4* ring = sdyn4;                                   // RING*32 uint4
    unsigned* tail = (unsigned*)(sdyn4 + RING * MROW4);
    volatile unsigned* vflags = tail;                      // [RING]
    volatile unsigned* vsup   = tail + RING;               // [128]
    int* selList = (int*)(tail + RING + 128);              // [1024]
    volatile int* ctrl = (volatile int*)(tail + RING + 128 + 1024); // [16]
    // ctrl[0]=cons pos, ctrl[1]=done, ctrl[2]=sel, ctrl[3]=pad idx

    for (int i = t; i < RING + 128 + 16; i += 1024) {
        if (i < RING) vflags[i] = 0u;
        else if (i < RING + 128) vsup[i - RING] = 0u;
        else ctrl[i - RING - 128] = 0;
    }
    __syncthreads();

    const uint4* mbase = g_mask4 + (size_t)b * CAND * MROW4;

    if (warp >= 1) {
        // -------- producers: warp p handles rows p-1, p-1+NPROD, ... --------
        for (int r = warp - 1; r < CAND; r += NPROD) {
            int stop = 0;
            if (lane == 0) {
                while (r >= ctrl[0] + RING && !ctrl[1]) {}
                if (ctrl[1]) stop = 1;
            }
            stop = __shfl_sync(0xffffffffu, stop, 0);
            if (stop) break;
            // dead-row skip: if consumer already suppressed r, no load needed
            unsigned supw = vsup[r >> 5];
            if (!((supw >> (r & 31)) & 1u)) {
                ring[(r % RING) * MROW4 + lane] = mbase[(size_t)r * MROW4 + lane];
                __threadfence_block();
            }
            __syncwarp();
            if (lane == 0) vflags[r % RING] = (unsigned)(r + 1);
        }
    } else {
        // -------- consumer: register-resident 4000-bit suppressed mask ------
        unsigned m0 = 0, m1 = 0, m2 = 0, m3 = 0;   // lane L owns words 4L..4L+3
        int sel = 0;
        for (int w = 0; w < NWORD && sel < POSTK; ++w) {
            if (lane == 0) ctrl[0] = w * 32;
            unsigned v = (w & 3) == 0 ? m0 : (w & 3) == 1 ? m1 : (w & 3) == 2 ? m2 : m3;
            unsigned cur = __shfl_sync(0xffffffffu, v, w >> 2);
            unsigned alive = ~cur;
            while (alive && sel < POSTK) {
                int bit = __ffs(alive) - 1;
                int i = w * 32 + bit;
                if (lane == 0) { while (vflags[i % RING] != (unsigned)(i + 1)) {} }
                __syncwarp();
                const volatile unsigned* rr =
                    (const volatile unsigned*)(ring + (i % RING) * MROW4) + lane * 4;
                m0 |= rr[0]; m1 |= rr[1]; m2 |= rr[2]; m3 |= rr[3];
                // publish suppressed state for producer dead-skip
                vsup[lane * 4 + 0] = m0; vsup[lane * 4 + 1] = m1;
                vsup[lane * 4 + 2] = m2; vsup[lane * 4 + 3] = m3;
                if (lane == 0) selList[sel] = i;
                sel++;
                unsigned v2 = (w & 3) == 0 ? m0 : (w & 3) == 1 ? m1 : (w & 3) == 2 ? m2 : m3;
                unsigned curw = __shfl_sync(0xffffffffu, v2, w >> 2);
                alive &= ~curw;
                alive &= ~(1u << bit);
            }
        }
        if (lane == 0) { ctrl[1] = 1; ctrl[2] = sel; }
    }
    __syncthreads();

    // -------- parallel output epilogue --------
    if (t == 0) {
        int p = 0;
        while (g_slvl[b * CAND + p] != 0) ++p;   // concat position 0 = 1st lvl-0
        ctrl[3] = p;
    }
    __syncthreads();
    int sel = ctrl[2];
    int padi = ctrl[3];
    for (int r = t; r < POSTK; r += 1024) {
        int src = (r < sel) ? selList[r] : padi;
        float4 bx = g_sbox[b * CAND + src];
        float sc = g_sscore[b * CAND + src];
        float* o = out + ((size_t)b * POSTK + r) * 5;
        o[0] = bx.x; o[1] = bx.y; o[2] = bx.z; o[3] = bx.w; o[4] = sc;
    }
}

// ---------------------------------------------------------------------------
extern "C" void kernel_launch(void* const* d_in, const int* in_sizes, int n_in,
                              void* d_out, int out_size) {
    const float* lg0 = (const float*)d_in[0];
    const float* dl0 = (const float*)d_in[1];
    const float* lg1 = (const float*)d_in[2];
    const float* dl1 = (const float*)d_in[3];
    const float* an0 = (const float*)d_in[4];
    const float* an1 = (const float*)d_in[5];
    float* out = (float*)d_out;

    zero_kernel<<<(NUNITS * NB16 + 1023) / 1024, 1024>>>();
    hist_kernel<<<NUNITS * HSLICE, 1024>>>(lg0, lg1);
    thresh_kernel<<<NUNITS, 1024>>>(lg0, lg1);
    sortdecode_kernel<<<BATCH, 1024>>>(lg0, dl0, lg1, dl1, an0, an1);
    mask_kernel<<<BATCH * 250, 256>>>();
    cudaFuncSetAttribute(scan_kernel, cudaFuncAttributeMaxDynamicSharedMemorySize, SCAN_SMEM);
    scan_kernel<<<BATCH, 1024, SCAN_SMEM>>>(out);
}

// round 10
// speedup vs baseline: 1.1353x; 1.0122x over previous
#include <cuda_runtime.h>
#include <math.h>

#define BATCH 8
#define M0 228000
#define M1 57000
#define KSEL 2000
#define CAND 4000
#define POSTK 1000
#define IMG_Wf 1216.0f
#define IMG_Hf 800.0f
#define LVL_OFF 1217.0f
#define SCALE_CLAMPF 4.135166556742356f
#define NMS_T 0.7f
#define NWORD 125            /* 4000/32 */
#define MROW  128            /* padded words per mask row (512B = 32 uint4) */
#define MROW4 32             /* uint4 per mask row */
#define RING  256            /* ring slots: 256*512B = 128KB */
#define NPROD 31             /* producer warps 0..30; consumer = warp 31 */
#define NUNITS 16
#define NB16 65536
#define HSLICE 14
#define TIECAP 4096

#define SCAN_SMEM (RING * 512 + (RING + 128 + 1024 + 16) * 4)

// ---------------- scratch (device globals; no allocation allowed) ----------
__device__ unsigned g_hist[NUNITS * NB16];            // 4 MB (zeroed at load;
                                                      // thresh re-zeroes per run)
__device__ int      g_cand[BATCH * CAND];
__device__ float4   g_sbox[BATCH * CAND];
__device__ float4   g_snb [BATCH * CAND];
__device__ float    g_sarea[BATCH * CAND];
__device__ float    g_sscore[BATCH * CAND];
__device__ int      g_slvl[BATCH * CAND];
__device__ uint4    g_mask4[(size_t)BATCH * CAND * MROW4];   // 16 MB

__device__ __forceinline__ unsigned fkey(float f) {
    unsigned u = __float_as_uint(f);
    return (u & 0x80000000u) ? ~u : (u | 0x80000000u);
}
__device__ __forceinline__ float fkey_inv(unsigned u) {
    return (u & 0x80000000u) ? __uint_as_float(u & 0x7fffffffu)
                             : __uint_as_float(~u);
}
__device__ __forceinline__ unsigned long long shfl_xor_u64(unsigned long long v, int j) {
    unsigned lo = (unsigned)v, hi = (unsigned)(v >> 32);
    lo = __shfl_xor_sync(0xffffffffu, lo, j);
    hi = __shfl_xor_sync(0xffffffffu, hi, j);
    return ((unsigned long long)hi << 32) | lo;
}

// ---------------- K0: chip-wide 16-bit histogram per (image, level) --------
__global__ void hist_kernel(const float* __restrict__ lg0,
                            const float* __restrict__ lg1) {
    int unit = blockIdx.x / HSLICE;
    int slice = blockIdx.x % HSLICE;
    int b = unit >> 1, lvl = unit & 1;
    const float* lg = lvl ? (lg1 + (size_t)b * M1) : (lg0 + (size_t)b * M0);
    int M4 = (lvl ? M1 : M0) >> 2;
    const float4* lg4 = (const float4*)lg;
    unsigned* H = g_hist + unit * NB16;

    int chunk = (M4 + HSLICE - 1) / HSLICE;
    int s = slice * chunk;
    int e = s + chunk; if (e > M4) e = M4;
    for (int i = s + threadIdx.x; i < e; i += 1024) {
        float4 v = lg4[i];
        atomicAdd(&H[fkey(v.x) >> 16], 1u);
        atomicAdd(&H[fkey(v.y) >> 16], 1u);
        atomicAdd(&H[fkey(v.z) >> 16], 1u);
        atomicAdd(&H[fkey(v.w) >> 16], 1u);
    }
}

// ---------------- K1: threshold + tie-rank + compaction per unit -----------
__global__ void thresh_kernel(const float* __restrict__ lg0,
                              const float* __restrict__ lg1) {
    int unit = blockIdx.x;
    int b = unit >> 1, lvl = unit & 1;
    const float* lg = lvl ? (lg1 + (size_t)b * M1) : (lg0 + (size_t)b * M0);
    int M4 = (lvl ? M1 : M0) >> 2;
    const float4* lg4 = (const float4*)lg;
    unsigned* H = g_hist + unit * NB16;
    int t = threadIdx.x;

    __shared__ unsigned chunkSum[1024];
    __shared__ int sh_chunk, sh_nBefore, sh_T16, sh_ngt, sh_cnt, sh_nTie;
    __shared__ unsigned long long tieKey[TIECAP];   // 32 KB

    unsigned s = 0;
    #pragma unroll 8
    for (int j = 0; j < 64; ++j) s += H[t * 64 + j];
    chunkSum[t] = s;
    if (t == 0) { sh_cnt = 0; sh_nTie = 0; }
    __syncthreads();
    if (t == 0) {
        unsigned cum = 0;
        for (int tt = 1023; tt >= 0; --tt) {
            if (cum + chunkSum[tt] >= KSEL) { sh_chunk = tt; sh_nBefore = (int)cum; break; }
            cum += chunkSum[tt];
        }
    }
    __syncthreads();
    if (t == sh_chunk) {
        unsigned cum = (unsigned)sh_nBefore;
        for (int j = 63; j >= 0; --j) {
            unsigned c = H[t * 64 + j];
            if (cum + c >= KSEL) { sh_T16 = t * 64 + j; sh_ngt = (int)cum; break; }
            cum += c;
        }
    }
    __syncthreads();
    // re-zero histogram for the next graph replay (replaces zero_kernel)
    #pragma unroll 8
    for (int j = 0; j < 64; ++j) H[t * 64 + j] = 0u;

    unsigned T16 = (unsigned)sh_T16;
    int n_gt = sh_ngt;
    int kRem = KSEL - n_gt;
    int base = b * CAND + lvl * KSEL;

    for (int i4 = t; i4 < M4; i4 += 1024) {
        float4 v = lg4[i4];
        int i = i4 * 4;
        unsigned uu[4] = { fkey(v.x), fkey(v.y), fkey(v.z), fkey(v.w) };
        #pragma unroll
        for (int c = 0; c < 4; ++c) {
            unsigned h = uu[c] >> 16;
            if (h > T16) {
                int sl = atomicAdd(&sh_cnt, 1);
                g_cand[base + sl] = (lvl << 18) | (i + c);
            } else if (h == T16) {
                int sl = atomicAdd(&sh_nTie, 1);
                if (sl < TIECAP)
                    tieKey[sl] = ((unsigned long long)uu[c] << 32) |
                                 (unsigned)(~(unsigned)(i + c));
            }
        }
    }
    __syncthreads();

    int n = sh_nTie < TIECAP ? sh_nTie : TIECAP;
    for (int e = t; e < n; e += 1024) {
        unsigned long long k = tieKey[e];
        int r = 0;
        for (int c = 0; c < n; ++c) r += (tieKey[c] > k);
        if (r < kRem) {
            int idx = (int)(~(unsigned)k);
            g_cand[base + n_gt + r] = (lvl << 18) | idx;
        }
    }
}

// ---------------- K2: per-image hybrid bitonic sort + decode ---------------
__global__ void sortdecode_kernel(const float* __restrict__ lg0, const float* __restrict__ dl0,
                                  const float* __restrict__ lg1, const float* __restrict__ dl1,
                                  const float* __restrict__ an0, const float* __restrict__ an1) {
    int b = blockIdx.x, t = threadIdx.x;
    int lane = t & 31, warp = t >> 5;
    __shared__ unsigned long long key[4096];

    for (int i = t; i < 4096; i += 1024) {
        if (i < CAND) {
            int p = g_cand[b * CAND + i];
            int lvl = p >> 18, idx = p & 0x3ffff;
            float sc = lvl ? lg1[(size_t)b * M1 + idx] : lg0[(size_t)b * M0 + idx];
            key[i] = ((unsigned long long)fkey(sc) << 32) | (unsigned)(~(unsigned)p);
        } else key[i] = 0ull;
    }
    __syncthreads();

    // ---- stage A: k = 2..32 fully in-register (each warp owns 4 blocks)
    for (int blk = warp; blk < 128; blk += 32) {
        unsigned long long v = key[blk * 32 + lane];
        #pragma unroll
        for (int k = 2; k <= 16; k <<= 1) {
            bool desc = ((lane & k) == 0);
            #pragma unroll
            for (int j = k >> 1; j > 0; j >>= 1) {
                unsigned long long o = shfl_xor_u64(v, j);
                bool lower = (lane & j) == 0;
                bool takeMax = (lower == desc);
                v = takeMax ? (v > o ? v : o) : (v < o ? v : o);
            }
        }
        {
            bool desc = ((blk & 1) == 0);   // (e & 32) == 0
            #pragma unroll
            for (int j = 16; j > 0; j >>= 1) {
                unsigned long long o = shfl_xor_u64(v, j);
                bool lower = (lane & j) == 0;
                bool takeMax = (lower == desc);
                v = takeMax ? (v > o ? v : o) : (v < o ? v : o);
            }
        }
        key[blk * 32 + lane] = v;
    }
    __syncthreads();

    // ---- stage B: k = 64..4096; smem for j>=32, registers for j<=16
    for (int k = 64; k <= 4096; k <<= 1) {
        for (int j = k >> 1; j >= 32; j >>= 1) {
            for (int e = t; e < 4096; e += 1024) {
                int ix = e ^ j;
                if (ix > e) {
                    unsigned long long a = key[e], bb = key[ix];
                    bool swp = ((e & k) == 0) ? (a < bb) : (a > bb);
                    if (swp) { key[e] = bb; key[ix] = a; }
                }
            }
            __syncthreads();
        }
        for (int blk = warp; blk < 128; blk += 32) {
            unsigned long long v = key[blk * 32 + lane];
            bool desc = (((blk * 32) & k) == 0);
            #pragma unroll
            for (int j = 16; j > 0; j >>= 1) {
                unsigned long long o = shfl_xor_u64(v, j);
                bool lower = (lane & j) == 0;
                bool takeMax = (lower == desc);
                v = takeMax ? (v > o ? v : o) : (v < o ? v : o);
            }
            key[blk * 32 + lane] = v;
        }
        __syncthreads();
    }

    // ---- decode in sorted order (strict per-op rounding, matches XLA)
    for (int i = t; i < CAND; i += 1024) {
        unsigned long long k = key[i];
        unsigned p = ~((unsigned)k);
        int lvl = (int)(p >> 18), idx = (int)(p & 0x3ffffu);
        float score = fkey_inv((unsigned)(k >> 32));

        const float* dl = lvl ? (dl1 + ((size_t)b * M1 + idx) * 4)
                              : (dl0 + ((size_t)b * M0 + idx) * 4);
        const float* an = (lvl ? an1 : an0) + (size_t)idx * 4;
        float4 a = *(const float4*)an;
        float4 d = *(const float4*)dl;

        float w  = __fsub_rn(a.z, a.x);
        float h  = __fsub_rn(a.w, a.y);
        float cx = __fadd_rn(a.x, __fmul_rn(0.5f, w));
        float cy = __fadd_rn(a.y, __fmul_rn(0.5f, h));
        float dw = fminf(d.z, SCALE_CLAMPF);
        float dh = fminf(d.w, SCALE_CLAMPF);
        float pcx = __fadd_rn(__fmul_rn(d.x, w), cx);
        float pcy = __fadd_rn(__fmul_rn(d.y, h), cy);
        float pw  = __fmul_rn(expf(dw), w);
        float ph  = __fmul_rn(expf(dh), h);
        float hpw = __fmul_rn(0.5f, pw);
        float hph = __fmul_rn(0.5f, ph);
        float x1 = __fsub_rn(pcx, hpw);
        float y1 = __fsub_rn(pcy, hph);
        float x2 = __fadd_rn(pcx, hpw);
        float y2 = __fadd_rn(pcy, hph);
        x1 = fminf(fmaxf(x1, 0.f), IMG_Wf);
        x2 = fminf(fmaxf(x2, 0.f), IMG_Wf);
        y1 = fminf(fmaxf(y1, 0.f), IMG_Hf);
        y2 = fminf(fmaxf(y2, 0.f), IMG_Hf);

        int gi = b * CAND + i;
        g_sbox[gi] = make_float4(x1, y1, x2, y2);
        float off = lvl ? LVL_OFF : 0.f;
        float nx1 = __fadd_rn(x1, off), ny1 = __fadd_rn(y1, off);
        float nx2 = __fadd_rn(x2, off), ny2 = __fadd_rn(y2, off);
        g_snb[gi]   = make_float4(nx1, ny1, nx2, ny2);
        g_sarea[gi] = __fmul_rn(__fsub_rn(nx2, nx1), __fsub_rn(ny2, ny1));
        g_sscore[gi] = score;
        g_slvl[gi]  = lvl;
    }
}

// ---------------- K3: 4000x4000 suppression bitmask per image --------------
__global__ void mask_kernel() {
    int blk = blockIdx.x;
    int b = blk / 250, rg = blk % 250;
    int t = threadIdx.x, wi = t >> 5, lane = t & 31;
    unsigned* gm = (unsigned*)g_mask4;

    for (int rr = 0; rr < 2; ++rr) {
        int row = rg * 16 + wi * 2 + rr;
        int gr = b * CAND + row;
        float4 jb = g_snb[gr];
        float  ja = g_sarea[gr];
        unsigned* mrow = gm + (size_t)gr * MROW;
        for (int w = 0; w < NWORD; ++w) {
            int col = b * CAND + w * 32 + lane;
            float4 nb = g_snb[col];
            float  na = g_sarea[col];
            float ix1 = fmaxf(jb.x, nb.x), iy1 = fmaxf(jb.y, nb.y);
            float ix2 = fminf(jb.z, nb.z), iy2 = fminf(jb.w, nb.w);
            float iw = fmaxf(__fsub_rn(ix2, ix1), 0.f);
            float ih = fmaxf(__fsub_rn(iy2, iy1), 0.f);
            float inter = __fmul_rn(iw, ih);
            float denom = fmaxf(__fsub_rn(__fadd_rn(ja, na), inter), 1e-6f);
            float iou = __fdiv_rn(inter, denom);
            unsigned bits = __ballot_sync(0xffffffffu, iou > NMS_T);
            if (lane == 0) mrow[w] = bits;
        }
    }
}

// ---------------- K4: serial sorted scan; consumer = warp 31 (hi prio) -----
__global__ void scan_kernel(float* __restrict__ out) {
    int b = blockIdx.x;
    int t = threadIdx.x, warp = t >> 5, lane = t & 31;

    extern __shared__ uint4 sdyn4[];
    uint4* ring = sdyn4;                                   // RING*32 uint4
    unsigned* tail = (unsigned*)(sdyn4 + RING * MROW4);
    volatile unsigned* vflags = tail;                      // [RING]
    volatile unsigned* vsup   = tail + RING;               // [128]
    int* selList = (int*)(tail + RING + 128);              // [1024]
    volatile int* ctrl = (volatile int*)(tail + RING + 128 + 1024); // [16]
    // ctrl[0]=cons pos, ctrl[1]=done, ctrl[2]=sel, ctrl[3]=pad idx

    for (int i = t; i < RING + 128 + 16; i += 1024) {
        if (i < RING) vflags[i] = 0u;
        else if (i < RING + 128) vsup[i - RING] = 0u;
        else ctrl[i - RING - 128] = 0;
    }
    __syncthreads();

    const uint4* mbase = g_mask4 + (size_t)b * CAND * MROW4;

    if (warp < NPROD) {
        // -------- producers (warps 0..30): warp p handles rows p, p+31, ... -
        for (int r = warp; r < CAND; r += NPROD) {
            int stop = 0;
            if (lane == 0) {
                while (r >= ctrl[0] + RING && !ctrl[1]) __nanosleep(200);
                if (ctrl[1]) stop = 1;
            }
            stop = __shfl_sync(0xffffffffu, stop, 0);
            if (stop) break;
            unsigned supw = vsup[r >> 5];
            if (!((supw >> (r & 31)) & 1u)) {
                ring[(r % RING) * MROW4 + lane] = mbase[(size_t)r * MROW4 + lane];
                __threadfence_block();
            }
            __syncwarp();
            if (lane == 0) vflags[r % RING] = (unsigned)(r + 1);
        }
    } else {
        // -------- consumer (warp 31 = highest issue priority) ---------------
        unsigned m0 = 0, m1 = 0, m2 = 0, m3 = 0;   // lane L owns words 4L..4L+3
        int sel = 0;
        for (int w = 0; w < NWORD && sel < POSTK; ++w) {
            if (lane == 0) ctrl[0] = w * 32;
            unsigned v = (w & 3) == 0 ? m0 : (w & 3) == 1 ? m1 : (w & 3) == 2 ? m2 : m3;
            unsigned cur = __shfl_sync(0xffffffffu, v, w >> 2);
            unsigned alive = ~cur;
            while (alive && sel < POSTK) {
                int bit = __ffs(alive) - 1;
                int i = w * 32 + bit;
                if (lane == 0) { while (vflags[i % RING] != (unsigned)(i + 1)) {} }
                __syncwarp();
                const volatile unsigned* rr =
                    (const volatile unsigned*)(ring + (i % RING) * MROW4) + lane * 4;
                m0 |= rr[0]; m1 |= rr[1]; m2 |= rr[2]; m3 |= rr[3];
                vsup[lane * 4 + 0] = m0; vsup[lane * 4 + 1] = m1;
                vsup[lane * 4 + 2] = m2; vsup[lane * 4 + 3] = m3;
                if (lane == 0) selList[sel] = i;
                sel++;
                unsigned v2 = (w & 3) == 0 ? m0 : (w & 3) == 1 ? m1 : (w & 3) == 2 ? m2 : m3;
                unsigned curw = __shfl_sync(0xffffffffu, v2, w >> 2);
                alive &= ~curw;
                alive &= ~(1u << bit);
            }
        }
        if (lane == 0) { ctrl[1] = 1; ctrl[2] = sel; }
    }
    __syncthreads();

    // -------- parallel output epilogue --------
    if (t == 0) {
        int p = 0;
        while (g_slvl[b * CAND + p] != 0) ++p;   // concat position 0 = 1st lvl-0
        ctrl[3] = p;
    }
    __syncthreads();
    int sel = ctrl[2];
    int padi = ctrl[3];
    for (int r = t; r < POSTK; r += 1024) {
        int src = (r < sel) ? selList[r] : padi;
        float4 bx = g_sbox[b * CAND + src];
        float sc = g_sscore[b * CAND + src];
        float* o = out + ((size_t)b * POSTK + r) * 5;
        o[0] = bx.x; o[1] = bx.y; o[2] = bx.z; o[3] = bx.w; o[4] = sc;
    }
}

// ---------------------------------------------------------------------------
extern "C" void kernel_launch(void* const* d_in, const int* in_sizes, int n_in,
                              void* d_out, int out_size) {
    const float* lg0 = (const float*)d_in[0];
    const float* dl0 = (const float*)d_in[1];
    const float* lg1 = (const float*)d_in[2];
    const float* dl1 = (const float*)d_in[3];
    const float* an0 = (const float*)d_in[4];
    const float* an1 = (const float*)d_in[5];
    float* out = (float*)d_out;

    hist_kernel<<<NUNITS * HSLICE, 1024>>>(lg0, lg1);
    thresh_kernel<<<NUNITS, 1024>>>(lg0, lg1);
    sortdecode_kernel<<<BATCH, 1024>>>(lg0, dl0, lg1, dl1, an0, an1);
    mask_kernel<<<BATCH * 250, 256>>>();
    cudaFuncSetAttribute(scan_kernel, cudaFuncAttributeMaxDynamicSharedMemorySize, SCAN_SMEM);
    scan_kernel<<<BATCH, 1024, SCAN_SMEM>>>(out);
}

// round 11
// speedup vs baseline: 1.2692x; 1.1179x over previous
#include <cuda_runtime.h>
#include <math.h>

#define BATCH 8
#define M0 228000
#define M1 57000
#define KSEL 2000
#define CAND 4000
#define POSTK 1000
#define IMG_Wf 1216.0f
#define IMG_Hf 800.0f
#define LVL_OFF 1217.0f
#define SCALE_CLAMPF 4.135166556742356f
#define NMS_T 0.7f
#define NWORD 125            /* 4000/32 */
#define MROW  128            /* padded words per mask row (512B = 32 uint4) */
#define MROW4 32             /* uint4 per mask row */
#define RING  256            /* ring slots: 256*512B = 128KB */
#define NPROD 31             /* producer warps 0..30; consumer = warp 31 */
#define NUNITS 16
#define NB16 65536
#define HSLICE 14
#define TIECAP 4096
#define MB_ROWS 16

#define SCAN_SMEM (RING * 512 + (RING + 128 + 1024 + 16) * 4)

// ---------------- scratch (device globals; no allocation allowed) ----------
__device__ unsigned g_hist[NUNITS * NB16];            // 4 MB (zeroed at load;
                                                      // thresh re-zeroes per run)
__device__ int      g_cand[BATCH * CAND];
__device__ float4   g_sbox[BATCH * CAND];
__device__ float4   g_snb [BATCH * CAND];
__device__ float    g_sarea[BATCH * CAND];
__device__ float    g_sscore[BATCH * CAND];
__device__ int      g_slvl[BATCH * CAND];
__device__ uint4    g_mask4[(size_t)BATCH * CAND * MROW4];   // 16 MB

__device__ __forceinline__ unsigned fkey(float f) {
    unsigned u = __float_as_uint(f);
    return (u & 0x80000000u) ? ~u : (u | 0x80000000u);
}
__device__ __forceinline__ float fkey_inv(unsigned u) {
    return (u & 0x80000000u) ? __uint_as_float(u & 0x7fffffffu)
                             : __uint_as_float(~u);
}
__device__ __forceinline__ unsigned long long shfl_xor_u64(unsigned long long v, int j) {
    unsigned lo = (unsigned)v, hi = (unsigned)(v >> 32);
    lo = __shfl_xor_sync(0xffffffffu, lo, j);
    hi = __shfl_xor_sync(0xffffffffu, hi, j);
    return ((unsigned long long)hi << 32) | lo;
}
__device__ __forceinline__ void st_release_cta(unsigned* p, unsigned v) {
    asm volatile("st.release.cta.u32 [%0], %1;" :: "l"(p), "r"(v) : "memory");
}
__device__ __forceinline__ unsigned ld_acquire_cta(unsigned* p) {
    unsigned v;
    asm volatile("ld.acquire.cta.u32 %0, [%1];" : "=r"(v) : "l"(p) : "memory");
    return v;
}

// ---------------- K0: chip-wide 16-bit histogram per (image, level) --------
__global__ void hist_kernel(const float* __restrict__ lg0,
                            const float* __restrict__ lg1) {
    int unit = blockIdx.x / HSLICE;
    int slice = blockIdx.x % HSLICE;
    int b = unit >> 1, lvl = unit & 1;
    const float* lg = lvl ? (lg1 + (size_t)b * M1) : (lg0 + (size_t)b * M0);
    int M4 = (lvl ? M1 : M0) >> 2;
    const float4* lg4 = (const float4*)lg;
    unsigned* H = g_hist + unit * NB16;

    int chunk = (M4 + HSLICE - 1) / HSLICE;
    int s = slice * chunk;
    int e = s + chunk; if (e > M4) e = M4;
    for (int i = s + threadIdx.x; i < e; i += 1024) {
        float4 v = lg4[i];
        atomicAdd(&H[fkey(v.x) >> 16], 1u);
        atomicAdd(&H[fkey(v.y) >> 16], 1u);
        atomicAdd(&H[fkey(v.z) >> 16], 1u);
        atomicAdd(&H[fkey(v.w) >> 16], 1u);
    }
}

// ---------------- K1: threshold + tie-rank + compaction per unit -----------
__global__ void thresh_kernel(const float* __restrict__ lg0,
                              const float* __restrict__ lg1) {
    int unit = blockIdx.x;
    int b = unit >> 1, lvl = unit & 1;
    const float* lg = lvl ? (lg1 + (size_t)b * M1) : (lg0 + (size_t)b * M0);
    int M4 = (lvl ? M1 : M0) >> 2;
    const float4* lg4 = (const float4*)lg;
    unsigned* H = g_hist + unit * NB16;
    int t = threadIdx.x;

    __shared__ unsigned chunkSum[1024];
    __shared__ int sh_chunk, sh_nBefore, sh_T16, sh_ngt, sh_cnt, sh_nTie;
    __shared__ unsigned long long tieKey[TIECAP];   // 32 KB

    unsigned s = 0;
    #pragma unroll 8
    for (int j = 0; j < 64; ++j) s += H[t * 64 + j];
    chunkSum[t] = s;
    if (t == 0) { sh_cnt = 0; sh_nTie = 0; }
    __syncthreads();
    if (t == 0) {
        unsigned cum = 0;
        for (int tt = 1023; tt >= 0; --tt) {
            if (cum + chunkSum[tt] >= KSEL) { sh_chunk = tt; sh_nBefore = (int)cum; break; }
            cum += chunkSum[tt];
        }
    }
    __syncthreads();
    if (t == sh_chunk) {
        unsigned cum = (unsigned)sh_nBefore;
        for (int j = 63; j >= 0; --j) {
            unsigned c = H[t * 64 + j];
            if (cum + c >= KSEL) { sh_T16 = t * 64 + j; sh_ngt = (int)cum; break; }
            cum += c;
        }
    }
    __syncthreads();
    // re-zero histogram for the next graph replay
    #pragma unroll 8
    for (int j = 0; j < 64; ++j) H[t * 64 + j] = 0u;

    unsigned T16 = (unsigned)sh_T16;
    int n_gt = sh_ngt;
    int kRem = KSEL - n_gt;
    int base = b * CAND + lvl * KSEL;

    for (int i4 = t; i4 < M4; i4 += 1024) {
        float4 v = lg4[i4];
        int i = i4 * 4;
        unsigned uu[4] = { fkey(v.x), fkey(v.y), fkey(v.z), fkey(v.w) };
        #pragma unroll
        for (int c = 0; c < 4; ++c) {
            unsigned h = uu[c] >> 16;
            if (h > T16) {
                int sl = atomicAdd(&sh_cnt, 1);
                g_cand[base + sl] = (lvl << 18) | (i + c);
            } else if (h == T16) {
                int sl = atomicAdd(&sh_nTie, 1);
                if (sl < TIECAP)
                    tieKey[sl] = ((unsigned long long)uu[c] << 32) |
                                 (unsigned)(~(unsigned)(i + c));
            }
        }
    }
    __syncthreads();

    int n = sh_nTie < TIECAP ? sh_nTie : TIECAP;
    for (int e = t; e < n; e += 1024) {
        unsigned long long k = tieKey[e];
        int r = 0;
        for (int c = 0; c < n; ++c) r += (tieKey[c] > k);
        if (r < kRem) {
            int idx = (int)(~(unsigned)k);
            g_cand[base + n_gt + r] = (lvl << 18) | idx;
        }
    }
}

// ---------------- K2: per-image hybrid bitonic sort + decode ---------------
__global__ void sortdecode_kernel(const float* __restrict__ lg0, const float* __restrict__ dl0,
                                  const float* __restrict__ lg1, const float* __restrict__ dl1,
                                  const float* __restrict__ an0, const float* __restrict__ an1) {
    int b = blockIdx.x, t = threadIdx.x;
    int lane = t & 31, warp = t >> 5;
    __shared__ unsigned long long key[4096];

    for (int i = t; i < 4096; i += 1024) {
        if (i < CAND) {
            int p = g_cand[b * CAND + i];
            int lvl = p >> 18, idx = p & 0x3ffff;
            float sc = lvl ? lg1[(size_t)b * M1 + idx] : lg0[(size_t)b * M0 + idx];
            key[i] = ((unsigned long long)fkey(sc) << 32) | (unsigned)(~(unsigned)p);
        } else key[i] = 0ull;
    }
    __syncthreads();

    // stage A: k = 2..32 fully in-register
    for (int blk = warp; blk < 128; blk += 32) {
        unsigned long long v = key[blk * 32 + lane];
        #pragma unroll
        for (int k = 2; k <= 16; k <<= 1) {
            bool desc = ((lane & k) == 0);
            #pragma unroll
            for (int j = k >> 1; j > 0; j >>= 1) {
                unsigned long long o = shfl_xor_u64(v, j);
                bool lower = (lane & j) == 0;
                bool takeMax = (lower == desc);
                v = takeMax ? (v > o ? v : o) : (v < o ? v : o);
            }
        }
        {
            bool desc = ((blk & 1) == 0);
            #pragma unroll
            for (int j = 16; j > 0; j >>= 1) {
                unsigned long long o = shfl_xor_u64(v, j);
                bool lower = (lane & j) == 0;
                bool takeMax = (lower == desc);
                v = takeMax ? (v > o ? v : o) : (v < o ? v : o);
            }
        }
        key[blk * 32 + lane] = v;
    }
    __syncthreads();

    // stage B: k = 64..4096; smem for j>=32, registers for j<=16
    for (int k = 64; k <= 4096; k <<= 1) {
        for (int j = k >> 1; j >= 32; j >>= 1) {
            for (int e = t; e < 4096; e += 1024) {
                int ix = e ^ j;
                if (ix > e) {
                    unsigned long long a = key[e], bb = key[ix];
                    bool swp = ((e & k) == 0) ? (a < bb) : (a > bb);
                    if (swp) { key[e] = bb; key[ix] = a; }
                }
            }
            __syncthreads();
        }
        for (int blk = warp; blk < 128; blk += 32) {
            unsigned long long v = key[blk * 32 + lane];
            bool desc = (((blk * 32) & k) == 0);
            #pragma unroll
            for (int j = 16; j > 0; j >>= 1) {
                unsigned long long o = shfl_xor_u64(v, j);
                bool lower = (lane & j) == 0;
                bool takeMax = (lower == desc);
                v = takeMax ? (v > o ? v : o) : (v < o ? v : o);
            }
            key[blk * 32 + lane] = v;
        }
        __syncthreads();
    }

    // decode in sorted order (strict per-op rounding, matches XLA)
    for (int i = t; i < CAND; i += 1024) {
        unsigned long long k = key[i];
        unsigned p = ~((unsigned)k);
        int lvl = (int)(p >> 18), idx = (int)(p & 0x3ffffu);
        float score = fkey_inv((unsigned)(k >> 32));

        const float* dl = lvl ? (dl1 + ((size_t)b * M1 + idx) * 4)
                              : (dl0 + ((size_t)b * M0 + idx) * 4);
        const float* an = (lvl ? an1 : an0) + (size_t)idx * 4;
        float4 a = *(const float4*)an;
        float4 d = *(const float4*)dl;

        float w  = __fsub_rn(a.z, a.x);
        float h  = __fsub_rn(a.w, a.y);
        float cx = __fadd_rn(a.x, __fmul_rn(0.5f, w));
        float cy = __fadd_rn(a.y, __fmul_rn(0.5f, h));
        float dw = fminf(d.z, SCALE_CLAMPF);
        float dh = fminf(d.w, SCALE_CLAMPF);
        float pcx = __fadd_rn(__fmul_rn(d.x, w), cx);
        float pcy = __fadd_rn(__fmul_rn(d.y, h), cy);
        float pw  = __fmul_rn(expf(dw), w);
        float ph  = __fmul_rn(expf(dh), h);
        float hpw = __fmul_rn(0.5f, pw);
        float hph = __fmul_rn(0.5f, ph);
        float x1 = __fsub_rn(pcx, hpw);
        float y1 = __fsub_rn(pcy, hph);
        float x2 = __fadd_rn(pcx, hpw);
        float y2 = __fadd_rn(pcy, hph);
        x1 = fminf(fmaxf(x1, 0.f), IMG_Wf);
        x2 = fminf(fmaxf(x2, 0.f), IMG_Wf);
        y1 = fminf(fmaxf(y1, 0.f), IMG_Hf);
        y2 = fminf(fmaxf(y2, 0.f), IMG_Hf);

        int gi = b * CAND + i;
        g_sbox[gi] = make_float4(x1, y1, x2, y2);
        float off = lvl ? LVL_OFF : 0.f;
        float nx1 = __fadd_rn(x1, off), ny1 = __fadd_rn(y1, off);
        float nx2 = __fadd_rn(x2, off), ny2 = __fadd_rn(y2, off);
        g_snb[gi]   = make_float4(nx1, ny1, nx2, ny2);
        g_sarea[gi] = __fmul_rn(__fsub_rn(nx2, nx1), __fsub_rn(ny2, ny1));
        g_sscore[gi] = score;
        g_slvl[gi]  = lvl;
    }
}

// ---------------- K3: suppression bitmask; cols in registers, rows smem ----
__global__ void mask_kernel() {
    int blk = blockIdx.x;
    int b = blk / 250, rg = blk % 250;
    int t = threadIdx.x, wi = t >> 5, lane = t & 31;
    int rowBase = rg * MB_ROWS;

    __shared__ float4 rb[MB_ROWS];
    __shared__ float  ra[MB_ROWS];
    if (t < MB_ROWS) {
        rb[t] = g_snb[b * CAND + rowBase + t];
        ra[t] = g_sarea[b * CAND + rowBase + t];
    }
    __syncthreads();

    unsigned* gm = (unsigned*)g_mask4;
    for (int w = wi; w < NWORD; w += 8) {
        int col = b * CAND + w * 32 + lane;
        float4 nb = g_snb[col];
        float  na = g_sarea[col];
        size_t obase = (size_t)(b * CAND + rowBase) * MROW + w;
        #pragma unroll
        for (int r = 0; r < MB_ROWS; ++r) {
            float4 jb = rb[r];
            float  ja = ra[r];
            float ix1 = fmaxf(jb.x, nb.x), iy1 = fmaxf(jb.y, nb.y);
            float ix2 = fminf(jb.z, nb.z), iy2 = fminf(jb.w, nb.w);
            float iw = fmaxf(__fsub_rn(ix2, ix1), 0.f);
            float ih = fmaxf(__fsub_rn(iy2, iy1), 0.f);
            float inter = __fmul_rn(iw, ih);
            float denom = fmaxf(__fsub_rn(__fadd_rn(ja, na), inter), 1e-6f);
            float rc;
            asm("rcp.approx.f32 %0, %1;" : "=f"(rc) : "f"(denom));
            float q = __fmul_rn(inter, rc);
            bool over = q > NMS_T;
            bool border = fabsf(q - NMS_T) < 0.005f;
            if (__any_sync(0xffffffffu, border)) {        // rare, warp-uniform
                if (border) over = (__fdiv_rn(inter, denom) > NMS_T);
            }
            unsigned bits = __ballot_sync(0xffffffffu, over);
            if (lane == 0) gm[obase + (size_t)r * MROW] = bits;
        }
    }
}

// ---------------- K4: serial sorted scan; acquire/release ring -------------
__global__ void scan_kernel(float* __restrict__ out) {
    int b = blockIdx.x;
    int t = threadIdx.x, warp = t >> 5, lane = t & 31;

    extern __shared__ uint4 sdyn4[];
    uint4* ring = sdyn4;                                   // RING*32 uint4
    unsigned* tail = (unsigned*)(sdyn4 + RING * MROW4);
    unsigned* flags = tail;                                // [RING]
    volatile unsigned* vsup = tail + RING;                 // [128]
    int* selList = (int*)(tail + RING + 128);              // [1024]
    volatile int* ctrl = (volatile int*)(tail + RING + 128 + 1024); // [16]
    // ctrl[0]=cons pos, ctrl[1]=done, ctrl[2]=sel, ctrl[3]=pad idx

    for (int i = t; i < RING + 128 + 16; i += 1024) {
        if (i < RING) flags[i] = 0u;
        else if (i < RING + 128) vsup[i - RING] = 0u;
        else ctrl[i - RING - 128] = 0;
    }
    __syncthreads();

    const uint4* mbase = g_mask4 + (size_t)b * CAND * MROW4;

    if (warp < NPROD) {
        // -------- producers (warps 0..30) --------
        for (int r = warp; r < CAND; r += NPROD) {
            int stop = 0;
            if (lane == 0) {
                while (r >= ctrl[0] + RING && !ctrl[1]) __nanosleep(100);
                if (ctrl[1]) stop = 1;
            }
            stop = __shfl_sync(0xffffffffu, stop, 0);
            if (stop) break;
            unsigned supw = vsup[r >> 5];
            if (!((supw >> (r & 31)) & 1u))
                ring[(r % RING) * MROW4 + lane] = mbase[(size_t)r * MROW4 + lane];
            __syncwarp();                       // orders all lanes' STS
            if (lane == 0) st_release_cta(&flags[r % RING], (unsigned)(r + 1));
        }
    } else {
        // -------- consumer (warp 31) --------
        unsigned m0 = 0, m1 = 0, m2 = 0, m3 = 0;   // lane L owns words 4L..4L+3
        int sel = 0;
        for (int w = 0; w < NWORD && sel < POSTK; ++w) {
            if (lane == 0) ctrl[0] = w * 32;
            unsigned v = (w & 3) == 0 ? m0 : (w & 3) == 1 ? m1 : (w & 3) == 2 ? m2 : m3;
            unsigned cur = __shfl_sync(0xffffffffu, v, w >> 2);
            unsigned alive = ~cur;
            while (alive && sel < POSTK) {
                int bit = __ffs(alive) - 1;
                int i = w * 32 + bit;
                if (lane == 0) {
                    while (ld_acquire_cta(&flags[i % RING]) != (unsigned)(i + 1)) {}
                }
                __syncwarp();                   // acquire + warp order
                uint4 rv = ring[(i % RING) * MROW4 + lane];   // LDS.128
                m0 |= rv.x; m1 |= rv.y; m2 |= rv.z; m3 |= rv.w;
                if (lane == 0) selList[sel] = i;
                sel++;
                if ((sel & 15) == 0) {          // amortized dead-row publish
                    vsup[lane * 4 + 0] = m0; vsup[lane * 4 + 1] = m1;
                    vsup[lane * 4 + 2] = m2; vsup[lane * 4 + 3] = m3;
                }
                unsigned v2 = (w & 3) == 0 ? m0 : (w & 3) == 1 ? m1 : (w & 3) == 2 ? m2 : m3;
                unsigned curw = __shfl_sync(0xffffffffu, v2, w >> 2);
                alive &= ~curw;
                alive &= ~(1u << bit);
            }
        }
        if (lane == 0) { ctrl[1] = 1; ctrl[2] = sel; }
    }
    __syncthreads();

    // -------- parallel output epilogue --------
    if (t == 0) {
        int p = 0;
        while (g_slvl[b * CAND + p] != 0) ++p;   // concat position 0 = 1st lvl-0
        ctrl[3] = p;
    }
    __syncthreads();
    int sel = ctrl[2];
    int padi = ctrl[3];
    for (int r = t; r < POSTK; r += 1024) {
        int src = (r < sel) ? selList[r] : padi;
        float4 bx = g_sbox[b * CAND + src];
        float sc = g_sscore[b * CAND + src];
        float* o = out + ((size_t)b * POSTK + r) * 5;
        o[0] = bx.x; o[1] = bx.y; o[2] = bx.z; o[3] = bx.w; o[4] = sc;
    }
}

// ---------------------------------------------------------------------------
extern "C" void kernel_launch(void* const* d_in, const int* in_sizes, int n_in,
                              void* d_out, int out_size) {
    const float* lg0 = (const float*)d_in[0];
    const float* dl0 = (const float*)d_in[1];
    const float* lg1 = (const float*)d_in[2];
    const float* dl1 = (const float*)d_in[3];
    const float* an0 = (const float*)d_in[4];
    const float* an1 = (const float*)d_in[5];
    float* out = (float*)d_out;

    hist_kernel<<<NUNITS * HSLICE, 1024>>>(lg0, lg1);
    thresh_kernel<<<NUNITS, 1024>>>(lg0, lg1);
    sortdecode_kernel<<<BATCH, 1024>>>(lg0, dl0, lg1, dl1, an0, an1);
    mask_kernel<<<BATCH * 250, 256>>>();
    cudaFuncSetAttribute(scan_kernel, cudaFuncAttributeMaxDynamicSharedMemorySize, SCAN_SMEM);
    scan_kernel<<<BATCH, 1024, SCAN_SMEM>>>(out);
}

// round 12
// speedup vs baseline: 1.3331x; 1.0504x over previous
#include <cuda_runtime.h>
#include <math.h>

#define BATCH 8
#define M0 228000
#define M1 57000
#define KSEL 2000
#define CAND 4000
#define POSTK 1000
#define IMG_Wf 1216.0f
#define IMG_Hf 800.0f
#define LVL_OFF 1217.0f
#define SCALE_CLAMPF 4.135166556742356f
#define NMS_T 0.7f
#define NWORD 125            /* 4000/32 */
#define MROW  128            /* padded words per mask row (512B = 32 uint4) */
#define MROW4 32             /* uint4 per mask row */
#define NUNITS 16
#define NB16 65536
#define HSLICE 14
#define TIECAP 4096
#define MB_ROWS 16

// ---------------- scratch (device globals; no allocation allowed) ----------
__device__ unsigned g_hist[NUNITS * NB16];            // 4 MB (zeroed at load;
                                                      // thresh re-zeroes per run)
__device__ int      g_cand[BATCH * CAND];
__device__ float4   g_sbox[BATCH * CAND];
__device__ float4   g_snb [BATCH * CAND];
__device__ float    g_sarea[BATCH * CAND];
__device__ float    g_sscore[BATCH * CAND];
__device__ int      g_slvl[BATCH * CAND];
__device__ uint4    g_mask4[(size_t)BATCH * CAND * MROW4];   // 16 MB
                    // upper triangle only (w >= row/32); lower stays 0 forever

__device__ __forceinline__ unsigned fkey(float f) {
    unsigned u = __float_as_uint(f);
    return (u & 0x80000000u) ? ~u : (u | 0x80000000u);
}
__device__ __forceinline__ float fkey_inv(unsigned u) {
    return (u & 0x80000000u) ? __uint_as_float(u & 0x7fffffffu)
                             : __uint_as_float(~u);
}
__device__ __forceinline__ unsigned long long shfl_xor_u64(unsigned long long v, int j) {
    unsigned lo = (unsigned)v, hi = (unsigned)(v >> 32);
    lo = __shfl_xor_sync(0xffffffffu, lo, j);
    hi = __shfl_xor_sync(0xffffffffu, hi, j);
    return ((unsigned long long)hi << 32) | lo;
}

// ---------------- K0: chip-wide 16-bit histogram per (image, level) --------
__global__ void hist_kernel(const float* __restrict__ lg0,
                            const float* __restrict__ lg1) {
    int unit = blockIdx.x / HSLICE;
    int slice = blockIdx.x % HSLICE;
    int b = unit >> 1, lvl = unit & 1;
    const float* lg = lvl ? (lg1 + (size_t)b * M1) : (lg0 + (size_t)b * M0);
    int M4 = (lvl ? M1 : M0) >> 2;
    const float4* lg4 = (const float4*)lg;
    unsigned* H = g_hist + unit * NB16;

    int chunk = (M4 + HSLICE - 1) / HSLICE;
    int s = slice * chunk;
    int e = s + chunk; if (e > M4) e = M4;
    for (int i = s + threadIdx.x; i < e; i += 1024) {
        float4 v = lg4[i];
        atomicAdd(&H[fkey(v.x) >> 16], 1u);
        atomicAdd(&H[fkey(v.y) >> 16], 1u);
        atomicAdd(&H[fkey(v.z) >> 16], 1u);
        atomicAdd(&H[fkey(v.w) >> 16], 1u);
    }
}

// ---------------- K1: threshold + tie-rank + compaction per unit -----------
__global__ void thresh_kernel(const float* __restrict__ lg0,
                              const float* __restrict__ lg1) {
    int unit = blockIdx.x;
    int b = unit >> 1, lvl = unit & 1;
    const float* lg = lvl ? (lg1 + (size_t)b * M1) : (lg0 + (size_t)b * M0);
    int M4 = (lvl ? M1 : M0) >> 2;
    const float4* lg4 = (const float4*)lg;
    unsigned* H = g_hist + unit * NB16;
    int t = threadIdx.x;

    __shared__ unsigned chunkSum[1024];
    __shared__ int sh_chunk, sh_nBefore, sh_T16, sh_ngt, sh_cnt, sh_nTie;
    __shared__ unsigned long long tieKey[TIECAP];   // 32 KB

    unsigned s = 0;
    #pragma unroll 8
    for (int j = 0; j < 64; ++j) s += H[t * 64 + j];
    chunkSum[t] = s;
    if (t == 0) { sh_cnt = 0; sh_nTie = 0; }
    __syncthreads();
    if (t == 0) {
        unsigned cum = 0;
        for (int tt = 1023; tt >= 0; --tt) {
            if (cum + chunkSum[tt] >= KSEL) { sh_chunk = tt; sh_nBefore = (int)cum; break; }
            cum += chunkSum[tt];
        }
    }
    __syncthreads();
    if (t == sh_chunk) {
        unsigned cum = (unsigned)sh_nBefore;
        for (int j = 63; j >= 0; --j) {
            unsigned c = H[t * 64 + j];
            if (cum + c >= KSEL) { sh_T16 = t * 64 + j; sh_ngt = (int)cum; break; }
            cum += c;
        }
    }
    __syncthreads();
    // re-zero histogram for the next graph replay
    #pragma unroll 8
    for (int j = 0; j < 64; ++j) H[t * 64 + j] = 0u;

    unsigned T16 = (unsigned)sh_T16;
    int n_gt = sh_ngt;
    int kRem = KSEL - n_gt;
    int base = b * CAND + lvl * KSEL;

    for (int i4 = t; i4 < M4; i4 += 1024) {
        float4 v = lg4[i4];
        int i = i4 * 4;
        unsigned uu[4] = { fkey(v.x), fkey(v.y), fkey(v.z), fkey(v.w) };
        #pragma unroll
        for (int c = 0; c < 4; ++c) {
            unsigned h = uu[c] >> 16;
            if (h > T16) {
                int sl = atomicAdd(&sh_cnt, 1);
                g_cand[base + sl] = (lvl << 18) | (i + c);
            } else if (h == T16) {
                int sl = atomicAdd(&sh_nTie, 1);
                if (sl < TIECAP)
                    tieKey[sl] = ((unsigned long long)uu[c] << 32) |
                                 (unsigned)(~(unsigned)(i + c));
            }
        }
    }
    __syncthreads();

    int n = sh_nTie < TIECAP ? sh_nTie : TIECAP;
    for (int e = t; e < n; e += 1024) {
        unsigned long long k = tieKey[e];
        int r = 0;
        for (int c = 0; c < n; ++c) r += (tieKey[c] > k);
        if (r < kRem) {
            int idx = (int)(~(unsigned)k);
            g_cand[base + n_gt + r] = (lvl << 18) | idx;
        }
    }
}

// ---------------- K2: per-image hybrid bitonic sort + decode ---------------
__global__ void sortdecode_kernel(const float* __restrict__ lg0, const float* __restrict__ dl0,
                                  const float* __restrict__ lg1, const float* __restrict__ dl1,
                                  const float* __restrict__ an0, const float* __restrict__ an1) {
    int b = blockIdx.x, t = threadIdx.x;
    int lane = t & 31, warp = t >> 5;
    __shared__ unsigned long long key[4096];

    for (int i = t; i < 4096; i += 1024) {
        if (i < CAND) {
            int p = g_cand[b * CAND + i];
            int lvl = p >> 18, idx = p & 0x3ffff;
            float sc = lvl ? lg1[(size_t)b * M1 + idx] : lg0[(size_t)b * M0 + idx];
            key[i] = ((unsigned long long)fkey(sc) << 32) | (unsigned)(~(unsigned)p);
        } else key[i] = 0ull;
    }
    __syncthreads();

    // stage A: k = 2..32 fully in-register
    for (int blk = warp; blk < 128; blk += 32) {
        unsigned long long v = key[blk * 32 + lane];
        #pragma unroll
        for (int k = 2; k <= 16; k <<= 1) {
            bool desc = ((lane & k) == 0);
            #pragma unroll
            for (int j = k >> 1; j > 0; j >>= 1) {
                unsigned long long o = shfl_xor_u64(v, j);
                bool lower = (lane & j) == 0;
                bool takeMax = (lower == desc);
                v = takeMax ? (v > o ? v : o) : (v < o ? v : o);
            }
        }
        {
            bool desc = ((blk & 1) == 0);
            #pragma unroll
            for (int j = 16; j > 0; j >>= 1) {
                unsigned long long o = shfl_xor_u64(v, j);
                bool lower = (lane & j) == 0;
                bool takeMax = (lower == desc);
                v = takeMax ? (v > o ? v : o) : (v < o ? v : o);
            }
        }
        key[blk * 32 + lane] = v;
    }
    __syncthreads();

    // stage B: k = 64..4096; smem for j>=32, registers for j<=16
    for (int k = 64; k <= 4096; k <<= 1) {
        for (int j = k >> 1; j >= 32; j >>= 1) {
            for (int e = t; e < 4096; e += 1024) {
                int ix = e ^ j;
                if (ix > e) {
                    unsigned long long a = key[e], bb = key[ix];
                    bool swp = ((e & k) == 0) ? (a < bb) : (a > bb);
                    if (swp) { key[e] = bb; key[ix] = a; }
                }
            }
            __syncthreads();
        }
        for (int blk = warp; blk < 128; blk += 32) {
            unsigned long long v = key[blk * 32 + lane];
            bool desc = (((blk * 32) & k) == 0);
            #pragma unroll
            for (int j = 16; j > 0; j >>= 1) {
                unsigned long long o = shfl_xor_u64(v, j);
                bool lower = (lane & j) == 0;
                bool takeMax = (lower == desc);
                v = takeMax ? (v > o ? v : o) : (v < o ? v : o);
            }
            key[blk * 32 + lane] = v;
        }
        __syncthreads();
    }

    // decode in sorted order (strict per-op rounding, matches XLA)
    for (int i = t; i < CAND; i += 1024) {
        unsigned long long k = key[i];
        unsigned p = ~((unsigned)k);
        int lvl = (int)(p >> 18), idx = (int)(p & 0x3ffffu);
        float score = fkey_inv((unsigned)(k >> 32));

        const float* dl = lvl ? (dl1 + ((size_t)b * M1 + idx) * 4)
                              : (dl0 + ((size_t)b * M0 + idx) * 4);
        const float* an = (lvl ? an1 : an0) + (size_t)idx * 4;
        float4 a = *(const float4*)an;
        float4 d = *(const float4*)dl;

        float w  = __fsub_rn(a.z, a.x);
        float h  = __fsub_rn(a.w, a.y);
        float cx = __fadd_rn(a.x, __fmul_rn(0.5f, w));
        float cy = __fadd_rn(a.y, __fmul_rn(0.5f, h));
        float dw = fminf(d.z, SCALE_CLAMPF);
        float dh = fminf(d.w, SCALE_CLAMPF);
        float pcx = __fadd_rn(__fmul_rn(d.x, w), cx);
        float pcy = __fadd_rn(__fmul_rn(d.y, h), cy);
        float pw  = __fmul_rn(expf(dw), w);
        float ph  = __fmul_rn(expf(dh), h);
        float hpw = __fmul_rn(0.5f, pw);
        float hph = __fmul_rn(0.5f, ph);
        float x1 = __fsub_rn(pcx, hpw);
        float y1 = __fsub_rn(pcy, hph);
        float x2 = __fadd_rn(pcx, hpw);
        float y2 = __fadd_rn(pcy, hph);
        x1 = fminf(fmaxf(x1, 0.f), IMG_Wf);
        x2 = fminf(fmaxf(x2, 0.f), IMG_Wf);
        y1 = fminf(fmaxf(y1, 0.f), IMG_Hf);
        y2 = fminf(fmaxf(y2, 0.f), IMG_Hf);

        int gi = b * CAND + i;
        g_sbox[gi] = make_float4(x1, y1, x2, y2);
        float off = lvl ? LVL_OFF : 0.f;
        float nx1 = __fadd_rn(x1, off), ny1 = __fadd_rn(y1, off);
        float nx2 = __fadd_rn(x2, off), ny2 = __fadd_rn(y2, off);
        g_snb[gi]   = make_float4(nx1, ny1, nx2, ny2);
        g_sarea[gi] = __fmul_rn(__fsub_rn(nx2, nx1), __fsub_rn(ny2, ny1));
        g_sscore[gi] = score;
        g_slvl[gi]  = lvl;
    }
}

// ---------------- K3: UPPER-TRIANGLE suppression bitmask -------------------
// Only words w >= row/32 are consumed by the forward scan; lower triangle is
// never written (stays 0 from zero-init → deterministic across replays).
__global__ void mask_kernel() {
    int blk = blockIdx.x;
    int b = blk / 250, rg = blk % 250;
    int t = threadIdx.x, wi = t >> 5, lane = t & 31;
    int rowBase = rg * MB_ROWS;
    int wStart = rowBase >> 5;             // min diagonal word in this block

    __shared__ float4 rb[MB_ROWS];
    __shared__ float  ra[MB_ROWS];
    if (t < MB_ROWS) {
        rb[t] = g_snb[b * CAND + rowBase + t];
        ra[t] = g_sarea[b * CAND + rowBase + t];
    }
    __syncthreads();

    unsigned* gm = (unsigned*)g_mask4;
    for (int w = wStart + wi; w < NWORD; w += 8) {
        int col = b * CAND + w * 32 + lane;
        float4 nb = g_snb[col];
        float  na = g_sarea[col];
        size_t obase = (size_t)(b * CAND + rowBase) * MROW + w;
        #pragma unroll
        for (int r = 0; r < MB_ROWS; ++r) {
            float4 jb = rb[r];
            float  ja = ra[r];
            float ix1 = fmaxf(jb.x, nb.x), iy1 = fmaxf(jb.y, nb.y);
            float ix2 = fminf(jb.z, nb.z), iy2 = fminf(jb.w, nb.w);
            float iw = fmaxf(__fsub_rn(ix2, ix1), 0.f);
            float ih = fmaxf(__fsub_rn(iy2, iy1), 0.f);
            float inter = __fmul_rn(iw, ih);
            float denom = fmaxf(__fsub_rn(__fadd_rn(ja, na), inter), 1e-6f);
            float rc;
            asm("rcp.approx.f32 %0, %1;" : "=f"(rc) : "f"(denom));
            float q = __fmul_rn(inter, rc);
            bool over = q > NMS_T;
            bool border = fabsf(q - NMS_T) < 0.005f;
            if (__any_sync(0xffffffffu, border)) {        // rare, warp-uniform
                if (border) over = (__fdiv_rn(inter, denom) > NMS_T);
            }
            unsigned bits = __ballot_sync(0xffffffffu, over);
            if (lane == 0) gm[obase + (size_t)r * MROW] = bits;
        }
    }
}

// ---------------- K4: single-warp forward scan, no producers ---------------
// Per word w: diag[lane] = row(w*32+lane)[w] (prefetched one word ahead,
// selection-independent). Serial select = ffs+shfl+and. Accepted rows ORed
// into register mask via coalesced LDG.128 batches at word end.
__global__ void scan_kernel(float* __restrict__ out) {
    int b = blockIdx.x;
    int t = threadIdx.x, warp = t >> 5, lane = t & 31;
    __shared__ int selList[POSTK];
    __shared__ int sh_sel, sh_padi;

    const unsigned* mw = (const unsigned*)g_mask4 + (size_t)b * CAND * MROW;

    if (warp == 0) {
        unsigned m0 = 0, m1 = 0, m2 = 0, m3 = 0;   // lane L owns words 4L..4L+3
        int sel = 0;
        unsigned diag = mw[(size_t)lane * MROW];   // word 0 diag
        for (int w = 0; w < NWORD && sel < POSTK; ++w) {
            unsigned diagNext = 0;
            if (w + 1 < NWORD)
                diagNext = mw[(size_t)((w + 1) * 32 + lane) * MROW + (w + 1)];

            unsigned mv = (w & 3) == 0 ? m0 : (w & 3) == 1 ? m1 : (w & 3) == 2 ? m2 : m3;
            unsigned cur = __shfl_sync(0xffffffffu, mv, w >> 2);
            unsigned alive = ~cur;
            unsigned acc = 0;
            while (alive && sel < POSTK) {
                int bit = __ffs(alive) - 1;
                acc |= (1u << bit);
                if (lane == 0) selList[sel] = w * 32 + bit;
                sel++;
                unsigned rw = __shfl_sync(0xffffffffu, diag, bit);
                alive &= ~rw;
                alive &= ~(1u << bit);
            }
            // OR accepted rows (coalesced 512B each, high MLP)
            while (acc) {
                int bit = __ffs(acc) - 1; acc &= acc - 1;
                int i = w * 32 + bit;
                uint4 rv = *(const uint4*)(mw + (size_t)i * MROW + lane * 4);
                m0 |= rv.x; m1 |= rv.y; m2 |= rv.z; m3 |= rv.w;
            }
            diag = diagNext;
        }
        if (lane == 0) sh_sel = sel;
    }
    if (t == 0) {
        int p = 0;
        while (g_slvl[b * CAND + p] != 0) ++p;   // concat position 0 = 1st lvl-0
        sh_padi = p;
    }
    __syncthreads();

    // -------- parallel output epilogue (all 256 threads) --------
    int sel = sh_sel;
    int padi = sh_padi;
    for (int r = t; r < POSTK; r += blockDim.x) {
        int src = (r < sel) ? selList[r] : padi;
        float4 bx = g_sbox[b * CAND + src];
        float sc = g_sscore[b * CAND + src];
        float* o = out + ((size_t)b * POSTK + r) * 5;
        o[0] = bx.x; o[1] = bx.y; o[2] = bx.z; o[3] = bx.w; o[4] = sc;
    }
}

// ---------------------------------------------------------------------------
extern "C" void kernel_launch(void* const* d_in, const int* in_sizes, int n_in,
                              void* d_out, int out_size) {
    const float* lg0 = (const float*)d_in[0];
    const float* dl0 = (const float*)d_in[1];
    const float* lg1 = (const float*)d_in[2];
    const float* dl1 = (const float*)d_in[3];
    const float* an0 = (const float*)d_in[4];
    const float* an1 = (const float*)d_in[5];
    float* out = (float*)d_out;

    hist_kernel<<<NUNITS * HSLICE, 1024>>>(lg0, lg1);
    thresh_kernel<<<NUNITS, 1024>>>(lg0, lg1);
    sortdecode_kernel<<<BATCH, 1024>>>(lg0, dl0, lg1, dl1, an0, an1);
    mask_kernel<<<BATCH * 250, 256>>>();
    scan_kernel<<<BATCH, 256>>>(out);
}

// round 13
// speedup vs baseline: 1.7287x; 1.2968x over previous
#include <cuda_runtime.h>
#include <math.h>

#define BATCH 8
#define M0 228000
#define M1 57000
#define KSEL 2000
#define CAND 4000
#define POSTK 1000
#define IMG_Wf 1216.0f
#define IMG_Hf 800.0f
#define LVL_OFF 1217.0f
#define SCALE_CLAMPF 4.135166556742356f
#define NMS_T 0.7f
#define NWORD 125            /* 4000/32 */
#define MROW  128            /* padded words per mask row (512B = 32 uint4) */
#define MROW4 32             /* uint4 per mask row */
#define NUNITS 16
#define NB16 65536
#define HSLICE 14
#define TIECAP 4096
#define MB_ROWS 16

// ---------------- scratch (device globals; no allocation allowed) ----------
__device__ unsigned g_hist[NUNITS * NB16];            // 4 MB (zeroed at load;
                                                      // thresh re-zeroes per run)
__device__ int      g_cand[BATCH * CAND];
__device__ float4   g_sbox[BATCH * CAND];
__device__ float4   g_snb [BATCH * CAND];
__device__ float    g_sarea[BATCH * CAND];
__device__ float    g_sscore[BATCH * CAND];
__device__ int      g_slvl[BATCH * CAND];
__device__ uint4    g_mask4[(size_t)BATCH * CAND * MROW4];   // 16 MB
                    // upper triangle only (w >= row/32); lower stays 0 forever

__device__ __forceinline__ unsigned fkey(float f) {
    unsigned u = __float_as_uint(f);
    return (u & 0x80000000u) ? ~u : (u | 0x80000000u);
}
__device__ __forceinline__ float fkey_inv(unsigned u) {
    return (u & 0x80000000u) ? __uint_as_float(u & 0x7fffffffu)
                             : __uint_as_float(~u);
}
__device__ __forceinline__ unsigned long long shfl_xor_u64(unsigned long long v, int j) {
    unsigned lo = (unsigned)v, hi = (unsigned)(v >> 32);
    lo = __shfl_xor_sync(0xffffffffu, lo, j);
    hi = __shfl_xor_sync(0xffffffffu, hi, j);
    return ((unsigned long long)hi << 32) | lo;
}

// ---------------- K0: chip-wide 16-bit histogram per (image, level) --------
__global__ void hist_kernel(const float* __restrict__ lg0,
                            const float* __restrict__ lg1) {
    int unit = blockIdx.x / HSLICE;
    int slice = blockIdx.x % HSLICE;
    int b = unit >> 1, lvl = unit & 1;
    const float* lg = lvl ? (lg1 + (size_t)b * M1) : (lg0 + (size_t)b * M0);
    int M4 = (lvl ? M1 : M0) >> 2;
    const float4* lg4 = (const float4*)lg;
    unsigned* H = g_hist + unit * NB16;

    int chunk = (M4 + HSLICE - 1) / HSLICE;
    int s = slice * chunk;
    int e = s + chunk; if (e > M4) e = M4;
    for (int i = s + threadIdx.x; i < e; i += 1024) {
        float4 v = lg4[i];
        atomicAdd(&H[fkey(v.x) >> 16], 1u);
        atomicAdd(&H[fkey(v.y) >> 16], 1u);
        atomicAdd(&H[fkey(v.z) >> 16], 1u);
        atomicAdd(&H[fkey(v.w) >> 16], 1u);
    }
}

// ---------------- K1: threshold + tie-rank + compaction per unit -----------
__global__ void thresh_kernel(const float* __restrict__ lg0,
                              const float* __restrict__ lg1) {
    int unit = blockIdx.x;
    int b = unit >> 1, lvl = unit & 1;
    const float* lg = lvl ? (lg1 + (size_t)b * M1) : (lg0 + (size_t)b * M0);
    int M4 = (lvl ? M1 : M0) >> 2;
    const float4* lg4 = (const float4*)lg;
    unsigned* H = g_hist + unit * NB16;
    int t = threadIdx.x;

    __shared__ unsigned chunkSum[1024];
    __shared__ int sh_chunk, sh_nBefore, sh_T16, sh_ngt, sh_cnt, sh_nTie;
    __shared__ unsigned long long tieKey[TIECAP];   // 32 KB

    unsigned s = 0;
    #pragma unroll 8
    for (int j = 0; j < 64; ++j) s += H[t * 64 + j];
    chunkSum[t] = s;
    if (t == 0) { sh_cnt = 0; sh_nTie = 0; }
    __syncthreads();
    if (t == 0) {
        unsigned cum = 0;
        for (int tt = 1023; tt >= 0; --tt) {
            if (cum + chunkSum[tt] >= KSEL) { sh_chunk = tt; sh_nBefore = (int)cum; break; }
            cum += chunkSum[tt];
        }
    }
    __syncthreads();
    if (t == sh_chunk) {
        unsigned cum = (unsigned)sh_nBefore;
        for (int j = 63; j >= 0; --j) {
            unsigned c = H[t * 64 + j];
            if (cum + c >= KSEL) { sh_T16 = t * 64 + j; sh_ngt = (int)cum; break; }
            cum += c;
        }
    }
    __syncthreads();
    // re-zero histogram for the next graph replay
    #pragma unroll 8
    for (int j = 0; j < 64; ++j) H[t * 64 + j] = 0u;

    unsigned T16 = (unsigned)sh_T16;
    int n_gt = sh_ngt;
    int kRem = KSEL - n_gt;
    int base = b * CAND + lvl * KSEL;

    for (int i4 = t; i4 < M4; i4 += 1024) {
        float4 v = lg4[i4];
        int i = i4 * 4;
        unsigned uu[4] = { fkey(v.x), fkey(v.y), fkey(v.z), fkey(v.w) };
        #pragma unroll
        for (int c = 0; c < 4; ++c) {
            unsigned h = uu[c] >> 16;
            if (h > T16) {
                int sl = atomicAdd(&sh_cnt, 1);
                g_cand[base + sl] = (lvl << 18) | (i + c);
            } else if (h == T16) {
                int sl = atomicAdd(&sh_nTie, 1);
                if (sl < TIECAP)
                    tieKey[sl] = ((unsigned long long)uu[c] << 32) |
                                 (unsigned)(~(unsigned)(i + c));
            }
        }
    }
    __syncthreads();

    int n = sh_nTie < TIECAP ? sh_nTie : TIECAP;
    for (int e = t; e < n; e += 1024) {
        unsigned long long k = tieKey[e];
        int r = 0;
        for (int c = 0; c < n; ++c) r += (tieKey[c] > k);
        if (r < kRem) {
            int idx = (int)(~(unsigned)k);
            g_cand[base + n_gt + r] = (lvl << 18) | idx;
        }
    }
}

// ---------------- K2: per-image hybrid bitonic sort + decode ---------------
__global__ void sortdecode_kernel(const float* __restrict__ lg0, const float* __restrict__ dl0,
                                  const float* __restrict__ lg1, const float* __restrict__ dl1,
                                  const float* __restrict__ an0, const float* __restrict__ an1) {
    int b = blockIdx.x, t = threadIdx.x;
    int lane = t & 31, warp = t >> 5;
    __shared__ unsigned long long key[4096];

    for (int i = t; i < 4096; i += 1024) {
        if (i < CAND) {
            int p = g_cand[b * CAND + i];
            int lvl = p >> 18, idx = p & 0x3ffff;
            float sc = lvl ? lg1[(size_t)b * M1 + idx] : lg0[(size_t)b * M0 + idx];
            key[i] = ((unsigned long long)fkey(sc) << 32) | (unsigned)(~(unsigned)p);
        } else key[i] = 0ull;
    }
    __syncthreads();

    // stage A: k = 2..32 fully in-register
    for (int blk = warp; blk < 128; blk += 32) {
        unsigned long long v = key[blk * 32 + lane];
        #pragma unroll
        for (int k = 2; k <= 16; k <<= 1) {
            bool desc = ((lane & k) == 0);
            #pragma unroll
            for (int j = k >> 1; j > 0; j >>= 1) {
                unsigned long long o = shfl_xor_u64(v, j);
                bool lower = (lane & j) == 0;
                bool takeMax = (lower == desc);
                v = takeMax ? (v > o ? v : o) : (v < o ? v : o);
            }
        }
        {
            bool desc = ((blk & 1) == 0);
            #pragma unroll
            for (int j = 16; j > 0; j >>= 1) {
                unsigned long long o = shfl_xor_u64(v, j);
                bool lower = (lane & j) == 0;
                bool takeMax = (lower == desc);
                v = takeMax ? (v > o ? v : o) : (v < o ? v : o);
            }
        }
        key[blk * 32 + lane] = v;
    }
    __syncthreads();

    // stage B: k = 64..4096; smem for j>=32, registers for j<=16
    for (int k = 64; k <= 4096; k <<= 1) {
        for (int j = k >> 1; j >= 32; j >>= 1) {
            for (int e = t; e < 4096; e += 1024) {
                int ix = e ^ j;
                if (ix > e) {
                    unsigned long long a = key[e], bb = key[ix];
                    bool swp = ((e & k) == 0) ? (a < bb) : (a > bb);
                    if (swp) { key[e] = bb; key[ix] = a; }
                }
            }
            __syncthreads();
        }
        for (int blk = warp; blk < 128; blk += 32) {
            unsigned long long v = key[blk * 32 + lane];
            bool desc = (((blk * 32) & k) == 0);
            #pragma unroll
            for (int j = 16; j > 0; j >>= 1) {
                unsigned long long o = shfl_xor_u64(v, j);
                bool lower = (lane & j) == 0;
                bool takeMax = (lower == desc);
                v = takeMax ? (v > o ? v : o) : (v < o ? v : o);
            }
            key[blk * 32 + lane] = v;
        }
        __syncthreads();
    }

    // decode in sorted order (strict per-op rounding, matches XLA)
    for (int i = t; i < CAND; i += 1024) {
        unsigned long long k = key[i];
        unsigned p = ~((unsigned)k);
        int lvl = (int)(p >> 18), idx = (int)(p & 0x3ffffu);
        float score = fkey_inv((unsigned)(k >> 32));

        const float* dl = lvl ? (dl1 + ((size_t)b * M1 + idx) * 4)
                              : (dl0 + ((size_t)b * M0 + idx) * 4);
        const float* an = (lvl ? an1 : an0) + (size_t)idx * 4;
        float4 a = *(const float4*)an;
        float4 d = *(const float4*)dl;

        float w  = __fsub_rn(a.z, a.x);
        float h  = __fsub_rn(a.w, a.y);
        float cx = __fadd_rn(a.x, __fmul_rn(0.5f, w));
        float cy = __fadd_rn(a.y, __fmul_rn(0.5f, h));
        float dw = fminf(d.z, SCALE_CLAMPF);
        float dh = fminf(d.w, SCALE_CLAMPF);
        float pcx = __fadd_rn(__fmul_rn(d.x, w), cx);
        float pcy = __fadd_rn(__fmul_rn(d.y, h), cy);
        float pw  = __fmul_rn(expf(dw), w);
        float ph  = __fmul_rn(expf(dh), h);
        float hpw = __fmul_rn(0.5f, pw);
        float hph = __fmul_rn(0.5f, ph);
        float x1 = __fsub_rn(pcx, hpw);
        float y1 = __fsub_rn(pcy, hph);
        float x2 = __fadd_rn(pcx, hpw);
        float y2 = __fadd_rn(pcy, hph);
        x1 = fminf(fmaxf(x1, 0.f), IMG_Wf);
        x2 = fminf(fmaxf(x2, 0.f), IMG_Wf);
        y1 = fminf(fmaxf(y1, 0.f), IMG_Hf);
        y2 = fminf(fmaxf(y2, 0.f), IMG_Hf);

        int gi = b * CAND + i;
        g_sbox[gi] = make_float4(x1, y1, x2, y2);
        float off = lvl ? LVL_OFF : 0.f;
        float nx1 = __fadd_rn(x1, off), ny1 = __fadd_rn(y1, off);
        float nx2 = __fadd_rn(x2, off), ny2 = __fadd_rn(y2, off);
        g_snb[gi]   = make_float4(nx1, ny1, nx2, ny2);
        g_sarea[gi] = __fmul_rn(__fsub_rn(nx2, nx1), __fsub_rn(ny2, ny1));
        g_sscore[gi] = score;
        g_slvl[gi]  = lvl;
    }
}

// ---------------- K3: UPPER-TRIANGLE suppression bitmask -------------------
__global__ void __launch_bounds__(256, 4) mask_kernel() {
    int blk = blockIdx.x;
    int b = blk / 250, rg = blk % 250;
    int t = threadIdx.x, wi = t >> 5, lane = t & 31;
    int rowBase = rg * MB_ROWS;
    int wStart = rowBase >> 5;             // min diagonal word in this block

    __shared__ float4 rb[MB_ROWS];
    __shared__ float  ra[MB_ROWS];
    if (t < MB_ROWS) {
        rb[t] = g_snb[b * CAND + rowBase + t];
        ra[t] = g_sarea[b * CAND + rowBase + t];
    }
    __syncthreads();

    unsigned* gm = (unsigned*)g_mask4;
    for (int w = wStart + wi; w < NWORD; w += 8) {
        int col = b * CAND + w * 32 + lane;
        float4 nb = g_snb[col];
        float  na = g_sarea[col];
        size_t obase = (size_t)(b * CAND + rowBase) * MROW + w;
        #pragma unroll 4
        for (int r = 0; r < MB_ROWS; ++r) {
            float4 jb = rb[r];
            float  ja = ra[r];
            float ix1 = fmaxf(jb.x, nb.x), iy1 = fmaxf(jb.y, nb.y);
            float ix2 = fminf(jb.z, nb.z), iy2 = fminf(jb.w, nb.w);
            float iw = fmaxf(__fsub_rn(ix2, ix1), 0.f);
            float ih = fmaxf(__fsub_rn(iy2, iy1), 0.f);
            float inter = __fmul_rn(iw, ih);
            float denom = fmaxf(__fsub_rn(__fadd_rn(ja, na), inter), 1e-6f);
            float rc;
            asm("rcp.approx.f32 %0, %1;" : "=f"(rc) : "f"(denom));
            float q = __fmul_rn(inter, rc);
            bool over = q > NMS_T;
            bool border = fabsf(q - NMS_T) < 0.005f;
            if (__any_sync(0xffffffffu, border)) {        // rare, warp-uniform
                if (border) over = (__fdiv_rn(inter, denom) > NMS_T);
            }
            unsigned bits = __ballot_sync(0xffffffffu, over);
            if (lane == 0) gm[obase + (size_t)r * MROW] = bits;
        }
    }
}

// ---------------- K4: single-warp forward scan, batched row ORs ------------
__global__ void scan_kernel(float* __restrict__ out) {
    int b = blockIdx.x;
    int t = threadIdx.x, warp = t >> 5, lane = t & 31;
    __shared__ int selList[POSTK];
    __shared__ int sh_sel, sh_padi;

    const unsigned* mw = (const unsigned*)g_mask4 + (size_t)b * CAND * MROW;

    if (warp == 0) {
        unsigned m0 = 0, m1 = 0, m2 = 0, m3 = 0;   // lane L owns words 4L..4L+3
        int sel = 0;
        unsigned diag = mw[(size_t)lane * MROW];   // word 0 diag
        for (int w = 0; w < NWORD && sel < POSTK; ++w) {
            unsigned diagNext = 0;
            if (w + 1 < NWORD)
                diagNext = mw[(size_t)((w + 1) * 32 + lane) * MROW + (w + 1)];

            unsigned mv = (w & 3) == 0 ? m0 : (w & 3) == 1 ? m1 : (w & 3) == 2 ? m2 : m3;
            unsigned cur = __shfl_sync(0xffffffffu, mv, w >> 2);
            unsigned alive = ~cur;
            unsigned acc = 0;
            while (alive && sel < POSTK) {
                int bit = __ffs(alive) - 1;
                acc |= (1u << bit);
                if (lane == 0) selList[sel] = w * 32 + bit;
                sel++;
                unsigned rw = __shfl_sync(0xffffffffu, diag, bit);
                alive &= ~rw;
                alive &= ~(1u << bit);
            }
            // OR accepted rows: 8 independent LDG.128 per batch (MLP=8).
            // Duplicate fallback index is harmless (OR is idempotent).
            while (acc) {
                int idx[8];
                idx[0] = w * 32 + (__ffs(acc) - 1); acc &= acc - 1;
                #pragma unroll
                for (int u = 1; u < 8; ++u) {
                    if (acc) { idx[u] = w * 32 + (__ffs(acc) - 1); acc &= acc - 1; }
                    else idx[u] = idx[0];
                }
                uint4 rv[8];
                #pragma unroll
                for (int u = 0; u < 8; ++u)
                    rv[u] = *(const uint4*)(mw + (size_t)idx[u] * MROW + lane * 4);
                #pragma unroll
                for (int u = 0; u < 8; ++u) {
                    m0 |= rv[u].x; m1 |= rv[u].y; m2 |= rv[u].z; m3 |= rv[u].w;
                }
            }
            diag = diagNext;
        }
        if (lane == 0) sh_sel = sel;
    }
    if (t == 0) {
        int p = 0;
        while (g_slvl[b * CAND + p] != 0) ++p;   // concat position 0 = 1st lvl-0
        sh_padi = p;
    }
    __syncthreads();

    // -------- parallel output epilogue (all 256 threads) --------
    int sel = sh_sel;
    int padi = sh_padi;
    for (int r = t; r < POSTK; r += blockDim.x) {
        int src = (r < sel) ? selList[r] : padi;
        float4 bx = g_sbox[b * CAND + src];
        float sc = g_sscore[b * CAND + src];
        float* o = out + ((size_t)b * POSTK + r) * 5;
        o[0] = bx.x; o[1] = bx.y; o[2] = bx.z; o[3] = bx.w; o[4] = sc;
    }
}

// ---------------------------------------------------------------------------
extern "C" void kernel_launch(void* const* d_in, const int* in_sizes, int n_in,
                              void* d_out, int out_size) {
    const float* lg0 = (const float*)d_in[0];
    const float* dl0 = (const float*)d_in[1];
    const float* lg1 = (const float*)d_in[2];
    const float* dl1 = (const float*)d_in[3];
    const float* an0 = (const float*)d_in[4];
    const float* an1 = (const float*)d_in[5];
    float* out = (float*)d_out;

    hist_kernel<<<NUNITS * HSLICE, 1024>>>(lg0, lg1);
    thresh_kernel<<<NUNITS, 1024>>>(lg0, lg1);
    sortdecode_kernel<<<BATCH, 1024>>>(lg0, dl0, lg1, dl1, an0, an1);
    mask_kernel<<<BATCH * 250, 256>>>();
    scan_kernel<<<BATCH, 256>>>(out);
}

// round 14
// speedup vs baseline: 1.9261x; 1.1142x over previous
#include <cuda_runtime.h>
#include <math.h>

#define BATCH 8
#define M0 228000
#define M1 57000
#define KSEL 2000
#define CAND 4000
#define POSTK 1000
#define IMG_Wf 1216.0f
#define IMG_Hf 800.0f
#define LVL_OFF 1217.0f
#define SCALE_CLAMPF 4.135166556742356f
#define NMS_T 0.7f
#define NWORD 125            /* 4000/32 */
#define MROW  128            /* padded words per mask row (512B = 32 uint4) */
#define MROW4 32             /* uint4 per mask row */
#define NUNITS 16
#define NB12 4096            /* 12-bit coarse bins */
#define HSLICE 14
#define TIECAP 4096
#define MB_ROWS 16

// ---------------- scratch (device globals; no allocation allowed) ----------
__device__ unsigned g_hist[NUNITS * NB12];      // 256 KB; zeroed at load, K1 re-zeroes
__device__ unsigned g_T12[NUNITS];
__device__ int      g_cnt[NUNITS];              // >T slot counter (K1 zeroes)
__device__ int      g_tieCnt[NUNITS];
__device__ unsigned long long g_tie[NUNITS * TIECAP];   // 512 KB
__device__ int      g_cand[BATCH * CAND];
__device__ float4   g_sbox[BATCH * CAND];
__device__ float4   g_snb [BATCH * CAND];
__device__ float    g_sarea[BATCH * CAND];
__device__ float    g_sscore[BATCH * CAND];
__device__ int      g_slvl[BATCH * CAND];
__device__ uint4    g_mask4[(size_t)BATCH * CAND * MROW4];   // 16 MB
                    // upper triangle only (w >= row/32); lower stays 0 forever

__device__ __forceinline__ unsigned fkey(float f) {
    unsigned u = __float_as_uint(f);
    return (u & 0x80000000u) ? ~u : (u | 0x80000000u);
}
__device__ __forceinline__ float fkey_inv(unsigned u) {
    return (u & 0x80000000u) ? __uint_as_float(u & 0x7fffffffu)
                             : __uint_as_float(~u);
}
__device__ __forceinline__ unsigned long long shfl_xor_u64(unsigned long long v, int j) {
    unsigned lo = (unsigned)v, hi = (unsigned)(v >> 32);
    lo = __shfl_xor_sync(0xffffffffu, lo, j);
    hi = __shfl_xor_sync(0xffffffffu, hi, j);
    return ((unsigned long long)hi << 32) | lo;
}

// ---------------- K0: 12-bit smem histogram per (unit, slice) --------------
__global__ void histcoarse_kernel(const float* __restrict__ lg0,
                                  const float* __restrict__ lg1) {
    int unit = blockIdx.x / HSLICE;
    int slice = blockIdx.x % HSLICE;
    int b = unit >> 1, lvl = unit & 1;
    const float* lg = lvl ? (lg1 + (size_t)b * M1) : (lg0 + (size_t)b * M0);
    int M4 = (lvl ? M1 : M0) >> 2;
    const float4* lg4 = (const float4*)lg;
    int t = threadIdx.x;

    __shared__ unsigned sh[NB12];           // 16 KB
    for (int i = t; i < NB12; i += 1024) sh[i] = 0u;
    __syncthreads();

    int chunk = (M4 + HSLICE - 1) / HSLICE;
    int s = slice * chunk;
    int e = s + chunk; if (e > M4) e = M4;
    for (int i = s + t; i < e; i += 1024) {
        float4 v = lg4[i];
        atomicAdd(&sh[fkey(v.x) >> 20], 1u);
        atomicAdd(&sh[fkey(v.y) >> 20], 1u);
        atomicAdd(&sh[fkey(v.z) >> 20], 1u);
        atomicAdd(&sh[fkey(v.w) >> 20], 1u);
    }
    __syncthreads();
    unsigned* H = g_hist + unit * NB12;
    for (int i = t; i < NB12; i += 1024)
        if (sh[i]) atomicAdd(&H[i], sh[i]);
}

// ---------------- K1: threshold bin + zero for next replay -----------------
__global__ void prep_kernel() {
    int unit = blockIdx.x;
    unsigned* H = g_hist + unit * NB12;
    int t = threadIdx.x;
    __shared__ unsigned hcopy[NB12];
    for (int i = t; i < NB12; i += 1024) hcopy[i] = H[i];
    __syncthreads();
    if (t == 0) {
        unsigned cum = 0; int bsel = 0; unsigned before = 0;
        for (int bin = NB12 - 1; bin >= 0; --bin) {
            unsigned c = hcopy[bin];
            if (cum + c >= KSEL) { bsel = bin; before = cum; break; }
            cum += c;
        }
        g_T12[unit] = (unsigned)bsel;
        g_cnt[unit] = 0;
        g_tieCnt[unit] = 0;
        (void)before;
    }
    // re-zero for next graph replay
    for (int i = t; i < NB12; i += 1024) H[i] = 0u;
}

// ---------------- K2: chip-wide compaction (slot order irrelevant) ---------
__global__ void compact_kernel(const float* __restrict__ lg0,
                               const float* __restrict__ lg1) {
    int unit = blockIdx.x / HSLICE;
    int slice = blockIdx.x % HSLICE;
    int b = unit >> 1, lvl = unit & 1;
    const float* lg = lvl ? (lg1 + (size_t)b * M1) : (lg0 + (size_t)b * M0);
    int M4 = (lvl ? M1 : M0) >> 2;
    const float4* lg4 = (const float4*)lg;
    int t = threadIdx.x, lane = t & 31;
    unsigned T12 = g_T12[unit];
    int base = b * CAND + lvl * KSEL;

    int chunk = (M4 + HSLICE - 1) / HSLICE;
    int s = slice * chunk;
    int e = s + chunk; if (e > M4) e = M4;
    int iters = (e - s + 1023) >> 10;       // padded: full-warp ballots safe

    for (int it = 0; it < iters; ++it) {
        int i = s + it * 1024 + t;
        bool inb = (i < e);
        float4 v = inb ? lg4[i] : make_float4(0.f, 0.f, 0.f, 0.f);
        int ib = i * 4;
        unsigned uu[4] = { fkey(v.x), fkey(v.y), fkey(v.z), fkey(v.w) };
        #pragma unroll
        for (int c = 0; c < 4; ++c) {
            unsigned h = uu[c] >> 20;
            bool gt = inb && (h > T12);
            // warp-aggregated slot alloc (1 ATOMG per warp-instruction)
            unsigned bal = __ballot_sync(0xffffffffu, gt);
            if (bal) {
                int leader = __ffs(bal) - 1;
                int rank = __popc(bal & ((1u << lane) - 1u));
                int bslot = 0;
                if (lane == leader) bslot = atomicAdd(&g_cnt[unit], __popc(bal));
                bslot = __shfl_sync(0xffffffffu, bslot, leader);
                if (gt) g_cand[base + bslot + rank] = (lvl << 18) | (ib + c);
            }
            bool tie = inb && (h == T12);
            if (tie) {
                int sl = atomicAdd(&g_tieCnt[unit], 1);
                if (sl < TIECAP)
                    g_tie[unit * TIECAP + sl] =
                        ((unsigned long long)uu[c] << 32) |
                        (unsigned)(~(unsigned)(ib + c));
            }
        }
    }
}

// ---------------- K3: rank ties, fill remaining slots ----------------------
__global__ void tierank_kernel() {
    int unit = blockIdx.x;
    int b = unit >> 1, lvl = unit & 1;
    int t = threadIdx.x;
    int n_gt = g_cnt[unit];
    int kRem = KSEL - n_gt;
    int n = g_tieCnt[unit]; if (n > TIECAP) n = TIECAP;
    int base = b * CAND + lvl * KSEL;

    __shared__ unsigned long long tk[TIECAP];   // 32 KB
    for (int i = t; i < n; i += 1024) tk[i] = g_tie[unit * TIECAP + i];
    __syncthreads();

    for (int e = t; e < n; e += 1024) {
        unsigned long long k = tk[e];
        int r = 0;
        for (int c = 0; c < n; ++c) r += (tk[c] > k);
        if (r < kRem) {
            int idx = (int)(~(unsigned)k);
            g_cand[base + n_gt + r] = (lvl << 18) | idx;
        }
    }
}

// ---------------- K4: per-image hybrid bitonic sort + decode ---------------
__global__ void sortdecode_kernel(const float* __restrict__ lg0, const float* __restrict__ dl0,
                                  const float* __restrict__ lg1, const float* __restrict__ dl1,
                                  const float* __restrict__ an0, const float* __restrict__ an1) {
    int b = blockIdx.x, t = threadIdx.x;
    int lane = t & 31, warp = t >> 5;
    __shared__ unsigned long long key[4096];

    for (int i = t; i < 4096; i += 1024) {
        if (i < CAND) {
            int p = g_cand[b * CAND + i];
            int lvl = p >> 18, idx = p & 0x3ffff;
            float sc = lvl ? lg1[(size_t)b * M1 + idx] : lg0[(size_t)b * M0 + idx];
            key[i] = ((unsigned long long)fkey(sc) << 32) | (unsigned)(~(unsigned)p);
        } else key[i] = 0ull;
    }
    __syncthreads();

    // stage A: k = 2..32 fully in-register
    for (int blk = warp; blk < 128; blk += 32) {
        unsigned long long v = key[blk * 32 + lane];
        #pragma unroll
        for (int k = 2; k <= 16; k <<= 1) {
            bool desc = ((lane & k) == 0);
            #pragma unroll
            for (int j = k >> 1; j > 0; j >>= 1) {
                unsigned long long o = shfl_xor_u64(v, j);
                bool lower = (lane & j) == 0;
                bool takeMax = (lower == desc);
                v = takeMax ? (v > o ? v : o) : (v < o ? v : o);
            }
        }
        {
            bool desc = ((blk & 1) == 0);
            #pragma unroll
            for (int j = 16; j > 0; j >>= 1) {
                unsigned long long o = shfl_xor_u64(v, j);
                bool lower = (lane & j) == 0;
                bool takeMax = (lower == desc);
                v = takeMax ? (v > o ? v : o) : (v < o ? v : o);
            }
        }
        key[blk * 32 + lane] = v;
    }
    __syncthreads();

    // stage B: k = 64..4096; smem for j>=32, registers for j<=16
    for (int k = 64; k <= 4096; k <<= 1) {
        for (int j = k >> 1; j >= 32; j >>= 1) {
            for (int e = t; e < 4096; e += 1024) {
                int ix = e ^ j;
                if (ix > e) {
                    unsigned long long a = key[e], bb = key[ix];
                    bool swp = ((e & k) == 0) ? (a < bb) : (a > bb);
                    if (swp) { key[e] = bb; key[ix] = a; }
                }
            }
            __syncthreads();
        }
        for (int blk = warp; blk < 128; blk += 32) {
            unsigned long long v = key[blk * 32 + lane];
            bool desc = (((blk * 32) & k) == 0);
            #pragma unroll
            for (int j = 16; j > 0; j >>= 1) {
                unsigned long long o = shfl_xor_u64(v, j);
                bool lower = (lane & j) == 0;
                bool takeMax = (lower == desc);
                v = takeMax ? (v > o ? v : o) : (v < o ? v : o);
            }
            key[blk * 32 + lane] = v;
        }
        __syncthreads();
    }

    // decode in sorted order (strict per-op rounding, matches XLA)
    for (int i = t; i < CAND; i += 1024) {
        unsigned long long k = key[i];
        unsigned p = ~((unsigned)k);
        int lvl = (int)(p >> 18), idx = (int)(p & 0x3ffffu);
        float score = fkey_inv((unsigned)(k >> 32));

        const float* dl = lvl ? (dl1 + ((size_t)b * M1 + idx) * 4)
                              : (dl0 + ((size_t)b * M0 + idx) * 4);
        const float* an = (lvl ? an1 : an0) + (size_t)idx * 4;
        float4 a = *(const float4*)an;
        float4 d = *(const float4*)dl;

        float w  = __fsub_rn(a.z, a.x);
        float h  = __fsub_rn(a.w, a.y);
        float cx = __fadd_rn(a.x, __fmul_rn(0.5f, w));
        float cy = __fadd_rn(a.y, __fmul_rn(0.5f, h));
        float dw = fminf(d.z, SCALE_CLAMPF);
        float dh = fminf(d.w, SCALE_CLAMPF);
        float pcx = __fadd_rn(__fmul_rn(d.x, w), cx);
        float pcy = __fadd_rn(__fmul_rn(d.y, h), cy);
        float pw  = __fmul_rn(expf(dw), w);
        float ph  = __fmul_rn(expf(dh), h);
        float hpw = __fmul_rn(0.5f, pw);
        float hph = __fmul_rn(0.5f, ph);
        float x1 = __fsub_rn(pcx, hpw);
        float y1 = __fsub_rn(pcy, hph);
        float x2 = __fadd_rn(pcx, hpw);
        float y2 = __fadd_rn(pcy, hph);
        x1 = fminf(fmaxf(x1, 0.f), IMG_Wf);
        x2 = fminf(fmaxf(x2, 0.f), IMG_Wf);
        y1 = fminf(fmaxf(y1, 0.f), IMG_Hf);
        y2 = fminf(fmaxf(y2, 0.f), IMG_Hf);

        int gi = b * CAND + i;
        g_sbox[gi] = make_float4(x1, y1, x2, y2);
        float off = lvl ? LVL_OFF : 0.f;
        float nx1 = __fadd_rn(x1, off), ny1 = __fadd_rn(y1, off);
        float nx2 = __fadd_rn(x2, off), ny2 = __fadd_rn(y2, off);
        g_snb[gi]   = make_float4(nx1, ny1, nx2, ny2);
        g_sarea[gi] = __fmul_rn(__fsub_rn(nx2, nx1), __fsub_rn(ny2, ny1));
        g_sscore[gi] = score;
        g_slvl[gi]  = lvl;
    }
}

// ---------------- K5: UPPER-TRIANGLE suppression bitmask -------------------
__global__ void __launch_bounds__(256, 4) mask_kernel() {
    int blk = blockIdx.x;
    int b = blk / 250, rg = blk % 250;
    int t = threadIdx.x, wi = t >> 5, lane = t & 31;
    int rowBase = rg * MB_ROWS;
    int wStart = rowBase >> 5;             // min diagonal word in this block

    __shared__ float4 rb[MB_ROWS];
    __shared__ float  ra[MB_ROWS];
    if (t < MB_ROWS) {
        rb[t] = g_snb[b * CAND + rowBase + t];
        ra[t] = g_sarea[b * CAND + rowBase + t];
    }
    __syncthreads();

    unsigned* gm = (unsigned*)g_mask4;
    for (int w = wStart + wi; w < NWORD; w += 8) {
        int col = b * CAND + w * 32 + lane;
        float4 nb = g_snb[col];
        float  na = g_sarea[col];
        size_t obase = (size_t)(b * CAND + rowBase) * MROW + w;
        #pragma unroll 4
        for (int r = 0; r < MB_ROWS; ++r) {
            float4 jb = rb[r];
            float  ja = ra[r];
            float ix1 = fmaxf(jb.x, nb.x), iy1 = fmaxf(jb.y, nb.y);
            float ix2 = fminf(jb.z, nb.z), iy2 = fminf(jb.w, nb.w);
            float iw = fmaxf(__fsub_rn(ix2, ix1), 0.f);
            float ih = fmaxf(__fsub_rn(iy2, iy1), 0.f);
            float inter = __fmul_rn(iw, ih);
            float denom = fmaxf(__fsub_rn(__fadd_rn(ja, na), inter), 1e-6f);
            float rc;
            asm("rcp.approx.f32 %0, %1;" : "=f"(rc) : "f"(denom));
            float q = __fmul_rn(inter, rc);
            bool over = q > NMS_T;
            bool border = fabsf(q - NMS_T) < 0.005f;
            if (__any_sync(0xffffffffu, border)) {        // rare, warp-uniform
                if (border) over = (__fdiv_rn(inter, denom) > NMS_T);
            }
            unsigned bits = __ballot_sync(0xffffffffu, over);
            if (lane == 0) gm[obase + (size_t)r * MROW] = bits;
        }
    }
}

// ---------------- K6: single-warp forward scan, batched row ORs ------------
__global__ void scan_kernel(float* __restrict__ out) {
    int b = blockIdx.x;
    int t = threadIdx.x, warp = t >> 5, lane = t & 31;
    __shared__ int selList[POSTK];
    __shared__ int sh_sel, sh_padi;

    const unsigned* mw = (const unsigned*)g_mask4 + (size_t)b * CAND * MROW;

    if (warp == 0) {
        unsigned m0 = 0, m1 = 0, m2 = 0, m3 = 0;   // lane L owns words 4L..4L+3
        int sel = 0;
        unsigned diag = mw[(size_t)lane * MROW];   // word 0 diag
        for (int w = 0; w < NWORD && sel < POSTK; ++w) {
            unsigned diagNext = 0;
            if (w + 1 < NWORD)
                diagNext = mw[(size_t)((w + 1) * 32 + lane) * MROW + (w + 1)];

            unsigned mv = (w & 3) == 0 ? m0 : (w & 3) == 1 ? m1 : (w & 3) == 2 ? m2 : m3;
            unsigned cur = __shfl_sync(0xffffffffu, mv, w >> 2);
            unsigned alive = ~cur;
            unsigned acc = 0;
            while (alive && sel < POSTK) {
                int bit = __ffs(alive) - 1;
                acc |= (1u << bit);
                if (lane == 0) selList[sel] = w * 32 + bit;
                sel++;
                unsigned rw = __shfl_sync(0xffffffffu, diag, bit);
                alive &= ~rw;
                alive &= ~(1u << bit);
            }
            // OR accepted rows: 8 independent LDG.128 per batch (MLP=8).
            while (acc) {
                int idx[8];
                idx[0] = w * 32 + (__ffs(acc) - 1); acc &= acc - 1;
                #pragma unroll
                for (int u = 1; u < 8; ++u) {
                    if (acc) { idx[u] = w * 32 + (__ffs(acc) - 1); acc &= acc - 1; }
                    else idx[u] = idx[0];
                }
                uint4 rv[8];
                #pragma unroll
                for (int u = 0; u < 8; ++u)
                    rv[u] = *(const uint4*)(mw + (size_t)idx[u] * MROW + lane * 4);
                #pragma unroll
                for (int u = 0; u < 8; ++u) {
                    m0 |= rv[u].x; m1 |= rv[u].y; m2 |= rv[u].z; m3 |= rv[u].w;
                }
            }
            diag = diagNext;
        }
        if (lane == 0) sh_sel = sel;
    }
    if (t == 0) {
        int p = 0;
        while (g_slvl[b * CAND + p] != 0) ++p;   // concat position 0 = 1st lvl-0
        sh_padi = p;
    }
    __syncthreads();

    // -------- parallel output epilogue (all 256 threads) --------
    int sel = sh_sel;
    int padi = sh_padi;
    for (int r = t; r < POSTK; r += blockDim.x) {
        int src = (r < sel) ? selList[r] : padi;
        float4 bx = g_sbox[b * CAND + src];
        float sc = g_sscore[b * CAND + src];
        float* o = out + ((size_t)b * POSTK + r) * 5;
        o[0] = bx.x; o[1] = bx.y; o[2] = bx.z; o[3] = bx.w; o[4] = sc;
    }
}

// ---------------------------------------------------------------------------
extern "C" void kernel_launch(void* const* d_in, const int* in_sizes, int n_in,
                              void* d_out, int out_size) {
    const float* lg0 = (const float*)d_in[0];
    const float* dl0 = (const float*)d_in[1];
    const float* lg1 = (const float*)d_in[2];
    const float* dl1 = (const float*)d_in[3];
    const float* an0 = (const float*)d_in[4];
    const float* an1 = (const float*)d_in[5];
    float* out = (float*)d_out;

    histcoarse_kernel<<<NUNITS * HSLICE, 1024>>>(lg0, lg1);
    prep_kernel<<<NUNITS, 1024>>>();
    compact_kernel<<<NUNITS * HSLICE, 1024>>>(lg0, lg1);
    tierank_kernel<<<NUNITS, 1024>>>();
    sortdecode_kernel<<<BATCH, 1024>>>(lg0, dl0, lg1, dl1, an0, an1);
    mask_kernel<<<BATCH * 250, 256>>>();
    scan_kernel<<<BATCH, 256>>>(out);
}

// round 15
// speedup vs baseline: 2.1057x; 1.0933x over previous
#include <cuda_runtime.h>
#include <math.h>

#define BATCH 8
#define M0 228000
#define M1 57000
#define KSEL 2000
#define CAND 4000
#define POSTK 1000
#define IMG_Wf 1216.0f
#define IMG_Hf 800.0f
#define LVL_OFF 1217.0f
#define SCALE_CLAMPF 4.135166556742356f
#define NMS_T 0.7f
#define NWORD 125            /* 4000/32 */
#define MROW  128            /* padded words per mask row (512B = 32 uint4) */
#define MROW4 32             /* uint4 per mask row */
#define NUNITS 16
#define NB12 4096            /* 12-bit coarse bins */
#define HSLICE 14
#define TIECAP 4096
#define MB_ROWS 16

// ---------------- scratch (device globals; no allocation allowed) ----------
__device__ unsigned g_hist[NUNITS * NB12];      // 256 KB; zeroed at load, K1 re-zeroes
__device__ unsigned g_T12[NUNITS];
__device__ int      g_cnt[NUNITS];              // >T slot counter (K1 zeroes)
__device__ int      g_tieCnt[NUNITS];
__device__ unsigned long long g_tie[NUNITS * TIECAP];   // 512 KB
__device__ int      g_cand[BATCH * CAND];
__device__ float4   g_sbox[BATCH * CAND];
__device__ float4   g_snb [BATCH * CAND];
__device__ float    g_sarea[BATCH * CAND];
__device__ float    g_sscore[BATCH * CAND];
__device__ int      g_slvl[BATCH * CAND];
__device__ uint4    g_mask4[(size_t)BATCH * CAND * MROW4];   // 16 MB
                    // upper triangle only (w >= row/32); lower stays 0 forever

__device__ __forceinline__ unsigned fkey(float f) {
    unsigned u = __float_as_uint(f);
    return (u & 0x80000000u) ? ~u : (u | 0x80000000u);
}
__device__ __forceinline__ float fkey_inv(unsigned u) {
    return (u & 0x80000000u) ? __uint_as_float(u & 0x7fffffffu)
                             : __uint_as_float(~u);
}
__device__ __forceinline__ unsigned long long shfl_xor_u64(unsigned long long v, int j) {
    unsigned lo = (unsigned)v, hi = (unsigned)(v >> 32);
    lo = __shfl_xor_sync(0xffffffffu, lo, j);
    hi = __shfl_xor_sync(0xffffffffu, hi, j);
    return ((unsigned long long)hi << 32) | lo;
}

// ---------------- K0: 12-bit smem histogram per (unit, slice) --------------
__global__ void histcoarse_kernel(const float* __restrict__ lg0,
                                  const float* __restrict__ lg1) {
    int unit = blockIdx.x / HSLICE;
    int slice = blockIdx.x % HSLICE;
    int b = unit >> 1, lvl = unit & 1;
    const float* lg = lvl ? (lg1 + (size_t)b * M1) : (lg0 + (size_t)b * M0);
    int M4 = (lvl ? M1 : M0) >> 2;
    const float4* lg4 = (const float4*)lg;
    int t = threadIdx.x;

    __shared__ unsigned sh[NB12];           // 16 KB
    for (int i = t; i < NB12; i += 1024) sh[i] = 0u;
    __syncthreads();

    int chunk = (M4 + HSLICE - 1) / HSLICE;
    int s = slice * chunk;
    int e = s + chunk; if (e > M4) e = M4;
    for (int i = s + t; i < e; i += 1024) {
        float4 v = lg4[i];
        atomicAdd(&sh[fkey(v.x) >> 20], 1u);
        atomicAdd(&sh[fkey(v.y) >> 20], 1u);
        atomicAdd(&sh[fkey(v.z) >> 20], 1u);
        atomicAdd(&sh[fkey(v.w) >> 20], 1u);
    }
    __syncthreads();
    unsigned* H = g_hist + unit * NB12;
    for (int i = t; i < NB12; i += 1024)
        if (sh[i]) atomicAdd(&H[i], sh[i]);
}

// ---------------- K1: threshold bin + zero for next replay -----------------
__global__ void prep_kernel() {
    int unit = blockIdx.x;
    unsigned* H = g_hist + unit * NB12;
    int t = threadIdx.x;
    __shared__ unsigned hcopy[NB12];
    for (int i = t; i < NB12; i += 1024) hcopy[i] = H[i];
    __syncthreads();
    if (t == 0) {
        unsigned cum = 0; int bsel = 0;
        for (int bin = NB12 - 1; bin >= 0; --bin) {
            unsigned c = hcopy[bin];
            if (cum + c >= KSEL) { bsel = bin; break; }
            cum += c;
        }
        g_T12[unit] = (unsigned)bsel;
        g_cnt[unit] = 0;
        g_tieCnt[unit] = 0;
    }
    // re-zero for next graph replay
    for (int i = t; i < NB12; i += 1024) H[i] = 0u;
}

// ---------------- K2: chip-wide compaction (slot order irrelevant) ---------
__global__ void compact_kernel(const float* __restrict__ lg0,
                               const float* __restrict__ lg1) {
    int unit = blockIdx.x / HSLICE;
    int slice = blockIdx.x % HSLICE;
    int b = unit >> 1, lvl = unit & 1;
    const float* lg = lvl ? (lg1 + (size_t)b * M1) : (lg0 + (size_t)b * M0);
    int M4 = (lvl ? M1 : M0) >> 2;
    const float4* lg4 = (const float4*)lg;
    int t = threadIdx.x, lane = t & 31;
    unsigned T12 = g_T12[unit];
    int base = b * CAND + lvl * KSEL;

    int chunk = (M4 + HSLICE - 1) / HSLICE;
    int s = slice * chunk;
    int e = s + chunk; if (e > M4) e = M4;
    int iters = (e - s + 1023) >> 10;       // padded: full-warp ballots safe

    for (int it = 0; it < iters; ++it) {
        int i = s + it * 1024 + t;
        bool inb = (i < e);
        float4 v = inb ? lg4[i] : make_float4(0.f, 0.f, 0.f, 0.f);
        int ib = i * 4;
        unsigned uu[4] = { fkey(v.x), fkey(v.y), fkey(v.z), fkey(v.w) };
        #pragma unroll
        for (int c = 0; c < 4; ++c) {
            unsigned h = uu[c] >> 20;
            bool gt = inb && (h > T12);
            // warp-aggregated slot alloc (1 ATOMG per warp-instruction)
            unsigned bal = __ballot_sync(0xffffffffu, gt);
            if (bal) {
                int leader = __ffs(bal) - 1;
                int rank = __popc(bal & ((1u << lane) - 1u));
                int bslot = 0;
                if (lane == leader) bslot = atomicAdd(&g_cnt[unit], __popc(bal));
                bslot = __shfl_sync(0xffffffffu, bslot, leader);
                if (gt) g_cand[base + bslot + rank] = (lvl << 18) | (ib + c);
            }
            bool tie = inb && (h == T12);
            if (tie) {
                int sl = atomicAdd(&g_tieCnt[unit], 1);
                if (sl < TIECAP)
                    g_tie[unit * TIECAP + sl] =
                        ((unsigned long long)uu[c] << 32) |
                        (unsigned)(~(unsigned)(ib + c));
            }
        }
    }
}

// ---------------- K3: rank ties (chip-wide: 14 slices per unit) ------------
__global__ void tierank_kernel() {
    int unit = blockIdx.x / HSLICE;
    int slice = blockIdx.x % HSLICE;
    int b = unit >> 1, lvl = unit & 1;
    int t = threadIdx.x;
    int n_gt = g_cnt[unit];
    int kRem = KSEL - n_gt;
    int n = g_tieCnt[unit]; if (n > TIECAP) n = TIECAP;
    int base = b * CAND + lvl * KSEL;

    __shared__ unsigned long long tk[TIECAP];   // 32 KB
    for (int i = t; i < n; i += 1024) tk[i] = g_tie[unit * TIECAP + i];
    __syncthreads();

    int chunk = (n + HSLICE - 1) / HSLICE;
    int s = slice * chunk;
    int e = s + chunk; if (e > n) e = n;
    for (int idx_e = s + t; idx_e < e; idx_e += 1024) {
        unsigned long long k = tk[idx_e];
        int r = 0;
        for (int c = 0; c < n; ++c) r += (tk[c] > k);
        if (r < kRem) {
            int idx = (int)(~(unsigned)k);
            g_cand[base + n_gt + r] = (lvl << 18) | idx;
        }
    }
}

// ---------------- K4: per-image hybrid bitonic sort + decode ---------------
__global__ void sortdecode_kernel(const float* __restrict__ lg0, const float* __restrict__ dl0,
                                  const float* __restrict__ lg1, const float* __restrict__ dl1,
                                  const float* __restrict__ an0, const float* __restrict__ an1) {
    int b = blockIdx.x, t = threadIdx.x;
    int lane = t & 31, warp = t >> 5;
    __shared__ unsigned long long key[4096];

    for (int i = t; i < 4096; i += 1024) {
        if (i < CAND) {
            int p = g_cand[b * CAND + i];
            int lvl = p >> 18, idx = p & 0x3ffff;
            float sc = lvl ? lg1[(size_t)b * M1 + idx] : lg0[(size_t)b * M0 + idx];
            key[i] = ((unsigned long long)fkey(sc) << 32) | (unsigned)(~(unsigned)p);
        } else key[i] = 0ull;
    }
    __syncthreads();

    // stage A: k = 2..32 fully in-register
    for (int blk = warp; blk < 128; blk += 32) {
        unsigned long long v = key[blk * 32 + lane];
        #pragma unroll
        for (int k = 2; k <= 16; k <<= 1) {
            bool desc = ((lane & k) == 0);
            #pragma unroll
            for (int j = k >> 1; j > 0; j >>= 1) {
                unsigned long long o = shfl_xor_u64(v, j);
                bool lower = (lane & j) == 0;
                bool takeMax = (lower == desc);
                v = takeMax ? (v > o ? v : o) : (v < o ? v : o);
            }
        }
        {
            bool desc = ((blk & 1) == 0);
            #pragma unroll
            for (int j = 16; j > 0; j >>= 1) {
                unsigned long long o = shfl_xor_u64(v, j);
                bool lower = (lane & j) == 0;
                bool takeMax = (lower == desc);
                v = takeMax ? (v > o ? v : o) : (v < o ? v : o);
            }
        }
        key[blk * 32 + lane] = v;
    }
    __syncthreads();

    // stage B: k = 64..4096; smem for j>=32, registers for j<=16
    for (int k = 64; k <= 4096; k <<= 1) {
        for (int j = k >> 1; j >= 32; j >>= 1) {
            for (int e = t; e < 4096; e += 1024) {
                int ix = e ^ j;
                if (ix > e) {
                    unsigned long long a = key[e], bb = key[ix];
                    bool swp = ((e & k) == 0) ? (a < bb) : (a > bb);
                    if (swp) { key[e] = bb; key[ix] = a; }
                }
            }
            __syncthreads();
        }
        for (int blk = warp; blk < 128; blk += 32) {
            unsigned long long v = key[blk * 32 + lane];
            bool desc = (((blk * 32) & k) == 0);
            #pragma unroll
            for (int j = 16; j > 0; j >>= 1) {
                unsigned long long o = shfl_xor_u64(v, j);
                bool lower = (lane & j) == 0;
                bool takeMax = (lower == desc);
                v = takeMax ? (v > o ? v : o) : (v < o ? v : o);
            }
            key[blk * 32 + lane] = v;
        }
        __syncthreads();
    }

    // decode in sorted order (strict per-op rounding, matches XLA)
    for (int i = t; i < CAND; i += 1024) {
        unsigned long long k = key[i];
        unsigned p = ~((unsigned)k);
        int lvl = (int)(p >> 18), idx = (int)(p & 0x3ffffu);
        float score = fkey_inv((unsigned)(k >> 32));

        const float* dl = lvl ? (dl1 + ((size_t)b * M1 + idx) * 4)
                              : (dl0 + ((size_t)b * M0 + idx) * 4);
        const float* an = (lvl ? an1 : an0) + (size_t)idx * 4;
        float4 a = *(const float4*)an;
        float4 d = *(const float4*)dl;

        float w  = __fsub_rn(a.z, a.x);
        float h  = __fsub_rn(a.w, a.y);
        float cx = __fadd_rn(a.x, __fmul_rn(0.5f, w));
        float cy = __fadd_rn(a.y, __fmul_rn(0.5f, h));
        float dw = fminf(d.z, SCALE_CLAMPF);
        float dh = fminf(d.w, SCALE_CLAMPF);
        float pcx = __fadd_rn(__fmul_rn(d.x, w), cx);
        float pcy = __fadd_rn(__fmul_rn(d.y, h), cy);
        float pw  = __fmul_rn(expf(dw), w);
        float ph  = __fmul_rn(expf(dh), h);
        float hpw = __fmul_rn(0.5f, pw);
        float hph = __fmul_rn(0.5f, ph);
        float x1 = __fsub_rn(pcx, hpw);
        float y1 = __fsub_rn(pcy, hph);
        float x2 = __fadd_rn(pcx, hpw);
        float y2 = __fadd_rn(pcy, hph);
        x1 = fminf(fmaxf(x1, 0.f), IMG_Wf);
        x2 = fminf(fmaxf(x2, 0.f), IMG_Wf);
        y1 = fminf(fmaxf(y1, 0.f), IMG_Hf);
        y2 = fminf(fmaxf(y2, 0.f), IMG_Hf);

        int gi = b * CAND + i;
        g_sbox[gi] = make_float4(x1, y1, x2, y2);
        float off = lvl ? LVL_OFF : 0.f;
        float nx1 = __fadd_rn(x1, off), ny1 = __fadd_rn(y1, off);
        float nx2 = __fadd_rn(x2, off), ny2 = __fadd_rn(y2, off);
        g_snb[gi]   = make_float4(nx1, ny1, nx2, ny2);
        g_sarea[gi] = __fmul_rn(__fsub_rn(nx2, nx1), __fsub_rn(ny2, ny1));
        g_sscore[gi] = score;
        g_slvl[gi]  = lvl;
    }
}

// ---------------- K5: UPPER-TRIANGLE suppression bitmask -------------------
__global__ void __launch_bounds__(256, 4) mask_kernel() {
    int blk = blockIdx.x;
    int b = blk / 250, rg = blk % 250;
    int t = threadIdx.x, wi = t >> 5, lane = t & 31;
    int rowBase = rg * MB_ROWS;
    int wStart = rowBase >> 5;             // min diagonal word in this block

    __shared__ float4 rb[MB_ROWS];
    __shared__ float  ra[MB_ROWS];
    if (t < MB_ROWS) {
        rb[t] = g_snb[b * CAND + rowBase + t];
        ra[t] = g_sarea[b * CAND + rowBase + t];
    }
    __syncthreads();

    unsigned* gm = (unsigned*)g_mask4;
    for (int w = wStart + wi; w < NWORD; w += 8) {
        int col = b * CAND + w * 32 + lane;
        float4 nb = g_snb[col];
        float  na = g_sarea[col];
        size_t obase = (size_t)(b * CAND + rowBase) * MROW + w;
        #pragma unroll 4
        for (int r = 0; r < MB_ROWS; ++r) {
            float4 jb = rb[r];
            float  ja = ra[r];
            float ix1 = fmaxf(jb.x, nb.x), iy1 = fmaxf(jb.y, nb.y);
            float ix2 = fminf(jb.z, nb.z), iy2 = fminf(jb.w, nb.w);
            float iw = fmaxf(__fsub_rn(ix2, ix1), 0.f);
            float ih = fmaxf(__fsub_rn(iy2, iy1), 0.f);
            float inter = __fmul_rn(iw, ih);
            float denom = fmaxf(__fsub_rn(__fadd_rn(ja, na), inter), 1e-6f);
            float rc;
            asm("rcp.approx.f32 %0, %1;" : "=f"(rc) : "f"(denom));
            float q = __fmul_rn(inter, rc);
            bool over = q > NMS_T;
            bool border = fabsf(q - NMS_T) < 0.005f;
            if (__any_sync(0xffffffffu, border)) {        // rare, warp-uniform
                if (border) over = (__fdiv_rn(inter, denom) > NMS_T);
            }
            unsigned bits = __ballot_sync(0xffffffffu, over);
            if (lane == 0) gm[obase + (size_t)r * MROW] = bits;
        }
    }
}

// ---------------- K6: single-warp forward scan, batched row ORs ------------
__global__ void scan_kernel(float* __restrict__ out) {
    int b = blockIdx.x;
    int t = threadIdx.x, warp = t >> 5, lane = t & 31;
    __shared__ int selList[POSTK];
    __shared__ int sh_sel, sh_padi;

    const unsigned* mw = (const unsigned*)g_mask4 + (size_t)b * CAND * MROW;

    if (warp == 0) {
        unsigned m0 = 0, m1 = 0, m2 = 0, m3 = 0;   // lane L owns words 4L..4L+3
        int sel = 0;
        unsigned diag = mw[(size_t)lane * MROW];   // word 0 diag
        for (int w = 0; w < NWORD && sel < POSTK; ++w) {
            unsigned diagNext = 0;
            if (w + 1 < NWORD)
                diagNext = mw[(size_t)((w + 1) * 32 + lane) * MROW + (w + 1)];

            unsigned mv = (w & 3) == 0 ? m0 : (w & 3) == 1 ? m1 : (w & 3) == 2 ? m2 : m3;
            unsigned cur = __shfl_sync(0xffffffffu, mv, w >> 2);
            unsigned alive = ~cur;
            unsigned acc = 0;
            while (alive && sel < POSTK) {
                int bit = __ffs(alive) - 1;
                acc |= (1u << bit);
                if (lane == 0) selList[sel] = w * 32 + bit;
                sel++;
                unsigned rw = __shfl_sync(0xffffffffu, diag, bit);
                alive &= ~rw;
                alive &= ~(1u << bit);
            }
            // OR accepted rows: 8 independent LDG.128 per batch (MLP=8).
            while (acc) {
                int idx[8];
                idx[0] = w * 32 + (__ffs(acc) - 1); acc &= acc - 1;
                #pragma unroll
                for (int u = 1; u < 8; ++u) {
                    if (acc) { idx[u] = w * 32 + (__ffs(acc) - 1); acc &= acc - 1; }
                    else idx[u] = idx[0];
                }
                uint4 rv[8];
                #pragma unroll
                for (int u = 0; u < 8; ++u)
                    rv[u] = *(const uint4*)(mw + (size_t)idx[u] * MROW + lane * 4);
                #pragma unroll
                for (int u = 0; u < 8; ++u) {
                    m0 |= rv[u].x; m1 |= rv[u].y; m2 |= rv[u].z; m3 |= rv[u].w;
                }
            }
            diag = diagNext;
        }
        if (lane == 0) sh_sel = sel;
    }
    if (t == 0) {
        int p = 0;
        while (g_slvl[b * CAND + p] != 0) ++p;   // concat position 0 = 1st lvl-0
        sh_padi = p;
    }
    __syncthreads();

    // -------- parallel output epilogue (all 256 threads) --------
    int sel = sh_sel;
    int padi = sh_padi;
    for (int r = t; r < POSTK; r += blockDim.x) {
        int src = (r < sel) ? selList[r] : padi;
        float4 bx = g_sbox[b * CAND + src];
        float sc = g_sscore[b * CAND + src];
        float* o = out + ((size_t)b * POSTK + r) * 5;
        o[0] = bx.x; o[1] = bx.y; o[2] = bx.z; o[3] = bx.w; o[4] = sc;
    }
}

// ---------------------------------------------------------------------------
extern "C" void kernel_launch(void* const* d_in, const int* in_sizes, int n_in,
                              void* d_out, int out_size) {
    const float* lg0 = (const float*)d_in[0];
    const float* dl0 = (const float*)d_in[1];
    const float* lg1 = (const float*)d_in[2];
    const float* dl1 = (const float*)d_in[3];
    const float* an0 = (const float*)d_in[4];
    const float* an1 = (const float*)d_in[5];
    float* out = (float*)d_out;

    histcoarse_kernel<<<NUNITS * HSLICE, 1024>>>(lg0, lg1);
    prep_kernel<<<NUNITS, 1024>>>();
    compact_kernel<<<NUNITS * HSLICE, 1024>>>(lg0, lg1);
    tierank_kernel<<<NUNITS * HSLICE, 1024>>>();
    sortdecode_kernel<<<BATCH, 1024>>>(lg0, dl0, lg1, dl1, an0, an1);
    mask_kernel<<<BATCH * 250, 256>>>();
    scan_kernel<<<BATCH, 256>>>(out);
}

// round 16
// speedup vs baseline: 2.3066x; 1.0954x over previous
#include <cuda_runtime.h>
#include <math.h>

#define BATCH 8
#define M0 228000
#define M1 57000
#define KSEL 2000
#define CAND 4000
#define POSTK 1000
#define IMG_Wf 1216.0f
#define IMG_Hf 800.0f
#define LVL_OFF 1217.0f
#define SCALE_CLAMPF 4.135166556742356f
#define NMS_T 0.7f
#define IOU_C 0.411764705882352941f   /* 7/17 */
#define NWORD 125            /* 4000/32 */
#define MROW  128            /* padded words per mask row (512B = 32 uint4) */
#define MROW4 32             /* uint4 per mask row */
#define NUNITS 16
#define NB12 4096            /* 12-bit coarse bins */
#define HSLICE 14
#define TIECAP 4096
#define MB_ROWS 16

// ---------------- scratch (device globals; no allocation allowed) ----------
__device__ unsigned g_hist[NUNITS * NB12];      // zeroed at load; prep re-zeroes
__device__ unsigned g_T12[NUNITS];
__device__ int      g_cnt[NUNITS];
__device__ int      g_tieCnt[NUNITS];
__device__ unsigned long long g_tie[NUNITS * TIECAP];
__device__ int      g_cand[BATCH * CAND];
__device__ float4   g_sbox[BATCH * CAND];
__device__ float4   g_snb [BATCH * CAND];
__device__ float    g_sarea[BATCH * CAND];
__device__ float    g_sscore[BATCH * CAND];
__device__ int      g_slvl[BATCH * CAND];
__device__ uint4    g_mask4[(size_t)BATCH * CAND * MROW4];   // 16 MB
                    // upper triangle only (w >= row/32); lower stays 0 forever

__device__ __forceinline__ unsigned fkey(float f) {
    unsigned u = __float_as_uint(f);
    return (u & 0x80000000u) ? ~u : (u | 0x80000000u);
}
__device__ __forceinline__ float fkey_inv(unsigned u) {
    return (u & 0x80000000u) ? __uint_as_float(u & 0x7fffffffu)
                             : __uint_as_float(~u);
}
__device__ __forceinline__ unsigned long long shfl_xor_u64(unsigned long long v, int j) {
    unsigned lo = (unsigned)v, hi = (unsigned)(v >> 32);
    lo = __shfl_xor_sync(0xffffffffu, lo, j);
    hi = __shfl_xor_sync(0xffffffffu, hi, j);
    return ((unsigned long long)hi << 32) | lo;
}

// ---------------- K0: 12-bit smem histogram per (unit, slice) --------------
__global__ void histcoarse_kernel(const float* __restrict__ lg0,
                                  const float* __restrict__ lg1) {
    int unit = blockIdx.x / HSLICE;
    int slice = blockIdx.x % HSLICE;
    int b = unit >> 1, lvl = unit & 1;
    const float* lg = lvl ? (lg1 + (size_t)b * M1) : (lg0 + (size_t)b * M0);
    int M4 = (lvl ? M1 : M0) >> 2;
    const float4* lg4 = (const float4*)lg;
    int t = threadIdx.x;

    __shared__ unsigned sh[NB12];           // 16 KB
    for (int i = t; i < NB12; i += 1024) sh[i] = 0u;
    __syncthreads();

    int chunk = (M4 + HSLICE - 1) / HSLICE;
    int s = slice * chunk;
    int e = s + chunk; if (e > M4) e = M4;
    for (int i = s + t; i < e; i += 1024) {
        float4 v = lg4[i];
        atomicAdd(&sh[fkey(v.x) >> 20], 1u);
        atomicAdd(&sh[fkey(v.y) >> 20], 1u);
        atomicAdd(&sh[fkey(v.z) >> 20], 1u);
        atomicAdd(&sh[fkey(v.w) >> 20], 1u);
    }
    __syncthreads();
    unsigned* H = g_hist + unit * NB12;
    for (int i = t; i < NB12; i += 1024)
        if (sh[i]) atomicAdd(&H[i], sh[i]);
}

// ---------------- K1: threshold bin + zero for next replay -----------------
// FIXED: chunk size is NB12/1024 = 4 (was 64 -> OOB reads into neighbor
// units / g_tie garbage; replays silently relied on stale g_cand).
__global__ void prep_kernel() {
    int unit = blockIdx.x;
    unsigned* H = g_hist + unit * NB12;
    int t = threadIdx.x;
    __shared__ unsigned chunkSum[1024];

    unsigned s = 0;
    #pragma unroll
    for (int j = 0; j < 4; ++j) s += H[t * 4 + j];
    chunkSum[t] = s;
    __syncthreads();
    if (t == 0) {
        unsigned cum = 0; int bsel = 0;
        for (int tt = 1023; tt >= 0; --tt) {
            if (cum + chunkSum[tt] >= KSEL) {
                // descend into this 4-bin chunk
                for (int j = 3; j >= 0; --j) {
                    unsigned c = H[tt * 4 + j];
                    if (cum + c >= KSEL) { bsel = tt * 4 + j; break; }
                    cum += c;
                }
                break;
            }
            cum += chunkSum[tt];
        }
        g_T12[unit] = (unsigned)bsel;
        g_cnt[unit] = 0;
        g_tieCnt[unit] = 0;
    }
    __syncthreads();
    // re-zero for next graph replay (own unit only)
    for (int i = t; i < NB12; i += 1024) H[i] = 0u;
}

// ---------------- K2: chip-wide compaction (slot order irrelevant) ---------
__global__ void compact_kernel(const float* __restrict__ lg0,
                               const float* __restrict__ lg1) {
    int unit = blockIdx.x / HSLICE;
    int slice = blockIdx.x % HSLICE;
    int b = unit >> 1, lvl = unit & 1;
    const float* lg = lvl ? (lg1 + (size_t)b * M1) : (lg0 + (size_t)b * M0);
    int M4 = (lvl ? M1 : M0) >> 2;
    const float4* lg4 = (const float4*)lg;
    int t = threadIdx.x, lane = t & 31;
    unsigned T12 = g_T12[unit];
    int base = b * CAND + lvl * KSEL;

    int chunk = (M4 + HSLICE - 1) / HSLICE;
    int s = slice * chunk;
    int e = s + chunk; if (e > M4) e = M4;
    int iters = (e - s + 1023) >> 10;       // padded: full-warp ballots safe

    for (int it = 0; it < iters; ++it) {
        int i = s + it * 1024 + t;
        bool inb = (i < e);
        float4 v = inb ? lg4[i] : make_float4(0.f, 0.f, 0.f, 0.f);
        int ib = i * 4;
        unsigned uu[4] = { fkey(v.x), fkey(v.y), fkey(v.z), fkey(v.w) };
        #pragma unroll
        for (int c = 0; c < 4; ++c) {
            unsigned h = uu[c] >> 20;
            bool gt = inb && (h > T12);
            unsigned bal = __ballot_sync(0xffffffffu, gt);
            if (bal) {
                int leader = __ffs(bal) - 1;
                int rank = __popc(bal & ((1u << lane) - 1u));
                int bslot = 0;
                if (lane == leader) bslot = atomicAdd(&g_cnt[unit], __popc(bal));
                bslot = __shfl_sync(0xffffffffu, bslot, leader);
                if (gt) g_cand[base + bslot + rank] = (lvl << 18) | (ib + c);
            }
            bool tie = inb && (h == T12);
            if (tie) {
                int sl = atomicAdd(&g_tieCnt[unit], 1);
                if (sl < TIECAP)
                    g_tie[unit * TIECAP + sl] =
                        ((unsigned long long)uu[c] << 32) |
                        (unsigned)(~(unsigned)(ib + c));
            }
        }
    }
}

// ---------------- K3: rank ties (chip-wide: 14 slices per unit) ------------
__global__ void tierank_kernel() {
    int unit = blockIdx.x / HSLICE;
    int slice = blockIdx.x % HSLICE;
    int b = unit >> 1, lvl = unit & 1;
    int t = threadIdx.x;
    int n_gt = g_cnt[unit];
    int kRem = KSEL - n_gt;
    int n = g_tieCnt[unit]; if (n > TIECAP) n = TIECAP;
    int base = b * CAND + lvl * KSEL;

    __shared__ unsigned long long tk[TIECAP];   // 32 KB
    for (int i = t; i < n; i += 1024) tk[i] = g_tie[unit * TIECAP + i];
    __syncthreads();

    int chunk = (n + HSLICE - 1) / HSLICE;
    int s = slice * chunk;
    int e = s + chunk; if (e > n) e = n;
    for (int idx_e = s + t; idx_e < e; idx_e += 1024) {
        unsigned long long k = tk[idx_e];
        int r = 0;
        for (int c = 0; c < n; ++c) r += (tk[c] > k);
        if (r < kRem) {
            int idx = (int)(~(unsigned)k);
            g_cand[base + n_gt + r] = (lvl << 18) | idx;
        }
    }
}

// ---------------- K4: per-image hybrid bitonic sort + decode ---------------
__global__ void sortdecode_kernel(const float* __restrict__ lg0, const float* __restrict__ dl0,
                                  const float* __restrict__ lg1, const float* __restrict__ dl1,
                                  const float* __restrict__ an0, const float* __restrict__ an1) {
    int b = blockIdx.x, t = threadIdx.x;
    int lane = t & 31, warp = t >> 5;
    __shared__ unsigned long long key[4096];

    for (int i = t; i < 4096; i += 1024) {
        if (i < CAND) {
            int p = g_cand[b * CAND + i];
            int lvl = p >> 18, idx = p & 0x3ffff;
            float sc = lvl ? lg1[(size_t)b * M1 + idx] : lg0[(size_t)b * M0 + idx];
            key[i] = ((unsigned long long)fkey(sc) << 32) | (unsigned)(~(unsigned)p);
        } else key[i] = 0ull;
    }
    __syncthreads();

    // stage A: k = 2..32 fully in-register
    for (int blk = warp; blk < 128; blk += 32) {
        unsigned long long v = key[blk * 32 + lane];
        #pragma unroll
        for (int k = 2; k <= 16; k <<= 1) {
            bool desc = ((lane & k) == 0);
            #pragma unroll
            for (int j = k >> 1; j > 0; j >>= 1) {
                unsigned long long o = shfl_xor_u64(v, j);
                bool lower = (lane & j) == 0;
                bool takeMax = (lower == desc);
                v = takeMax ? (v > o ? v : o) : (v < o ? v : o);
            }
        }
        {
            bool desc = ((blk & 1) == 0);
            #pragma unroll
            for (int j = 16; j > 0; j >>= 1) {
                unsigned long long o = shfl_xor_u64(v, j);
                bool lower = (lane & j) == 0;
                bool takeMax = (lower == desc);
                v = takeMax ? (v > o ? v : o) : (v < o ? v : o);
            }
        }
        key[blk * 32 + lane] = v;
    }
    __syncthreads();

    // stage B: k = 64..4096; smem for j>=32, registers for j<=16
    for (int k = 64; k <= 4096; k <<= 1) {
        for (int j = k >> 1; j >= 32; j >>= 1) {
            for (int e = t; e < 4096; e += 1024) {
                int ix = e ^ j;
                if (ix > e) {
                    unsigned long long a = key[e], bb = key[ix];
                    bool swp = ((e & k) == 0) ? (a < bb) : (a > bb);
                    if (swp) { key[e] = bb; key[ix] = a; }
                }
            }
            __syncthreads();
        }
        for (int blk = warp; blk < 128; blk += 32) {
            unsigned long long v = key[blk * 32 + lane];
            bool desc = (((blk * 32) & k) == 0);
            #pragma unroll
            for (int j = 16; j > 0; j >>= 1) {
                unsigned long long o = shfl_xor_u64(v, j);
                bool lower = (lane & j) == 0;
                bool takeMax = (lower == desc);
                v = takeMax ? (v > o ? v : o) : (v < o ? v : o);
            }
            key[blk * 32 + lane] = v;
        }
        __syncthreads();
    }

    // zero counters for next replay (runs after tierank consumed them)
    if (b == 0 && t < NUNITS) { g_cnt[t] = 0; g_tieCnt[t] = 0; }

    // decode in sorted order (strict per-op rounding, matches XLA)
    for (int i = t; i < CAND; i += 1024) {
        unsigned long long k = key[i];
        unsigned p = ~((unsigned)k);
        int lvl = (int)(p >> 18), idx = (int)(p & 0x3ffffu);
        float score = fkey_inv((unsigned)(k >> 32));

        const float* dl = lvl ? (dl1 + ((size_t)b * M1 + idx) * 4)
                              : (dl0 + ((size_t)b * M0 + idx) * 4);
        const float* an = (lvl ? an1 : an0) + (size_t)idx * 4;
        float4 a = *(const float4*)an;
        float4 d = *(const float4*)dl;

        float w  = __fsub_rn(a.z, a.x);
        float h  = __fsub_rn(a.w, a.y);
        float cx = __fadd_rn(a.x, __fmul_rn(0.5f, w));
        float cy = __fadd_rn(a.y, __fmul_rn(0.5f, h));
        float dw = fminf(d.z, SCALE_CLAMPF);
        float dh = fminf(d.w, SCALE_CLAMPF);
        float pcx = __fadd_rn(__fmul_rn(d.x, w), cx);
        float pcy = __fadd_rn(__fmul_rn(d.y, h), cy);
        float pw  = __fmul_rn(expf(dw), w);
        float ph  = __fmul_rn(expf(dh), h);
        float hpw = __fmul_rn(0.5f, pw);
        float hph = __fmul_rn(0.5f, ph);
        float x1 = __fsub_rn(pcx, hpw);
        float y1 = __fsub_rn(pcy, hph);
        float x2 = __fadd_rn(pcx, hpw);
        float y2 = __fadd_rn(pcy, hph);
        x1 = fminf(fmaxf(x1, 0.f), IMG_Wf);
        x2 = fminf(fmaxf(x2, 0.f), IMG_Wf);
        y1 = fminf(fmaxf(y1, 0.f), IMG_Hf);
        y2 = fminf(fmaxf(y2, 0.f), IMG_Hf);

        int gi = b * CAND + i;
        g_sbox[gi] = make_float4(x1, y1, x2, y2);
        float off = lvl ? LVL_OFF : 0.f;
        float nx1 = __fadd_rn(x1, off), ny1 = __fadd_rn(y1, off);
        float nx2 = __fadd_rn(x2, off), ny2 = __fadd_rn(y2, off);
        g_snb[gi]   = make_float4(nx1, ny1, nx2, ny2);
        g_sarea[gi] = __fmul_rn(__fsub_rn(nx2, nx1), __fsub_rn(ny2, ny1));
        g_sscore[gi] = score;
        g_slvl[gi]  = lvl;
    }
}

// ---------------- K5: UPPER-TRIANGLE suppression bitmask -------------------
// Fast path: iou>0.7 <=> inter > (7/17)(areaJ+areaN) (exact algebra, denom>=0).
// Near-threshold / degenerate pairs fall back to the exact reference formula,
// so decisions are bit-identical.
__global__ void __launch_bounds__(256, 4) mask_kernel() {
    int blk = blockIdx.x;
    int b = blk / 250, rg = blk % 250;
    int t = threadIdx.x, wi = t >> 5, lane = t & 31;
    int rowBase = rg * MB_ROWS;
    int wStart = rowBase >> 5;             // min diagonal word in this block

    __shared__ float4 rb[MB_ROWS];
    __shared__ float  ra[MB_ROWS];         // exact areas (for fallback)
    __shared__ float  rs[MB_ROWS];         // scaled areas (fast path)
    if (t < MB_ROWS) {
        rb[t] = g_snb[b * CAND + rowBase + t];
        float av = g_sarea[b * CAND + rowBase + t];
        ra[t] = av;
        rs[t] = IOU_C * av;
    }
    __syncthreads();

    unsigned* gm = (unsigned*)g_mask4;
    for (int w = wStart + wi; w < NWORD; w += 8) {
        int col = b * CAND + w * 32 + lane;
        float4 nb = g_snb[col];
        float  na = g_sarea[col];
        float  ns = IOU_C * na;
        size_t obase = (size_t)(b * CAND + rowBase) * MROW + w;
        #pragma unroll 4
        for (int r = 0; r < MB_ROWS; ++r) {
            float4 jb = rb[r];
            float ix1 = fmaxf(jb.x, nb.x), iy1 = fmaxf(jb.y, nb.y);
            float ix2 = fminf(jb.z, nb.z), iy2 = fminf(jb.w, nb.w);
            float iw = fmaxf(__fsub_rn(ix2, ix1), 0.f);
            float ih = fmaxf(__fsub_rn(iy2, iy1), 0.f);
            float inter = __fmul_rn(iw, ih);
            float rhs = rs[r] + ns;
            bool over = inter > rhs;
            bool border = fabsf(inter - rhs) < (1e-3f * rhs + 1e-5f);
            if (__ballot_sync(0xffffffffu, border)) {     // rare
                if (border) {
                    float denom = fmaxf(__fsub_rn(__fadd_rn(ra[r], na), inter), 1e-6f);
                    over = (__fdiv_rn(inter, denom) > NMS_T);
                }
            }
            unsigned bits = __ballot_sync(0xffffffffu, over);
            if (lane == 0) gm[obase + (size_t)r * MROW] = bits;
        }
    }
}

// ---------------- K6: single-warp forward scan, batched row ORs ------------
__global__ void scan_kernel(float* __restrict__ out) {
    int b = blockIdx.x;
    int t = threadIdx.x, warp = t >> 5, lane = t & 31;
    __shared__ int selList[POSTK];
    __shared__ int sh_sel, sh_padi;

    const unsigned* mw = (const unsigned*)g_mask4 + (size_t)b * CAND * MROW;

    if (warp == 0) {
        unsigned m0 = 0, m1 = 0, m2 = 0, m3 = 0;   // lane L owns words 4L..4L+3
        int sel = 0;
        unsigned diag = mw[(size_t)lane * MROW];   // word 0 diag
        for (int w = 0; w < NWORD && sel < POSTK; ++w) {
            unsigned diagNext = 0;
            if (w + 1 < NWORD)
                diagNext = mw[(size_t)((w + 1) * 32 + lane) * MROW + (w + 1)];

            unsigned mv = (w & 3) == 0 ? m0 : (w & 3) == 1 ? m1 : (w & 3) == 2 ? m2 : m3;
            unsigned cur = __shfl_sync(0xffffffffu, mv, w >> 2);
            unsigned alive = ~cur;
            unsigned acc = 0;
            while (alive && sel < POSTK) {
                int bit = __ffs(alive) - 1;
                acc |= (1u << bit);
                if (lane == 0) selList[sel] = w * 32 + bit;
                sel++;
                unsigned rw = __shfl_sync(0xffffffffu, diag, bit);
                alive &= ~rw;
                alive &= ~(1u << bit);
            }
            // OR accepted rows: 8 independent LDG.128 per batch (MLP=8).
            while (acc) {
                int idx[8];
                idx[0] = w * 32 + (__ffs(acc) - 1); acc &= acc - 1;
                #pragma unroll
                for (int u = 1; u < 8; ++u) {
                    if (acc) { idx[u] = w * 32 + (__ffs(acc) - 1); acc &= acc - 1; }
                    else idx[u] = idx[0];
                }
                uint4 rv[8];
                #pragma unroll
                for (int u = 0; u < 8; ++u)
                    rv[u] = *(const uint4*)(mw + (size_t)idx[u] * MROW + lane * 4);
                #pragma unroll
                for (int u = 0; u < 8; ++u) {
                    m0 |= rv[u].x; m1 |= rv[u].y; m2 |= rv[u].z; m3 |= rv[u].w;
                }
            }
            diag = diagNext;
        }
        if (lane == 0) sh_sel = sel;
    }
    if (t == 0) {
        int p = 0;
        while (g_slvl[b * CAND + p] != 0) ++p;   // concat position 0 = 1st lvl-0
        sh_padi = p;
    }
    __syncthreads();

    // -------- parallel output epilogue (all 256 threads) --------
    int sel = sh_sel;
    int padi = sh_padi;
    for (int r = t; r < POSTK; r += blockDim.x) {
        int src = (r < sel) ? selList[r] : padi;
        float4 bx = g_sbox[b * CAND + src];
        float sc = g_sscore[b * CAND + src];
        float* o = out + ((size_t)b * POSTK + r) * 5;
        o[0] = bx.x; o[1] = bx.y; o[2] = bx.z; o[3] = bx.w; o[4] = sc;
    }
}

// ---------------------------------------------------------------------------
extern "C" void kernel_launch(void* const* d_in, const int* in_sizes, int n_in,
                              void* d_out, int out_size) {
    const float* lg0 = (const float*)d_in[0];
    const float* dl0 = (const float*)d_in[1];
    const float* lg1 = (const float*)d_in[2];
    const float* dl1 = (const float*)d_in[3];
    const float* an0 = (const float*)d_in[4];
    const float* an1 = (const float*)d_in[5];
    float* out = (float*)d_out;

    histcoarse_kernel<<<NUNITS * HSLICE, 1024>>>(lg0, lg1);
    prep_kernel<<<NUNITS, 1024>>>();
    compact_kernel<<<NUNITS * HSLICE, 1024>>>(lg0, lg1);
    tierank_kernel<<<NUNITS * HSLICE, 1024>>>();
    sortdecode_kernel<<<BATCH, 1024>>>(lg0, dl0, lg1, dl1, an0, an1);
    mask_kernel<<<BATCH * 250, 256>>>();
    scan_kernel<<<BATCH, 256>>>(out);
}

// round 17
// speedup vs baseline: 2.3673x; 1.0263x over previous
#include <cuda_runtime.h>
#include <math.h>

#define BATCH 8
#define M0 228000
#define M1 57000
#define KSEL 2000
#define CAND 4000
#define POSTK 1000
#define IMG_Wf 1216.0f
#define IMG_Hf 800.0f
#define LVL_OFF 1217.0f
#define SCALE_CLAMPF 4.135166556742356f
#define NMS_T 0.7f
#define IOU_C 0.411764705882352941f   /* 7/17 */
#define NWORD 125            /* 4000/32 */
#define MROW  128            /* padded words per mask row (512B = 32 uint4) */
#define MROW4 32             /* uint4 per mask row */
#define NUNITS 16
#define NB12 4096            /* 12-bit coarse bins */
#define HS_HIST 37           /* hist/compact slices per unit (592 blocks @512thr) */
#define TSLICE 14            /* tierank slices per unit */
#define TIECAP 4096
#define MB_ROWS 16

// ---------------- scratch (device globals; no allocation allowed) ----------
__device__ unsigned g_hist[NUNITS * NB12];      // zeroed at load; elected block re-zeroes
__device__ int      g_histDone[NUNITS];         // last-block election counter
__device__ unsigned g_T12[NUNITS];
__device__ int      g_cnt[NUNITS];
__device__ int      g_tieCnt[NUNITS];
__device__ unsigned long long g_tie[NUNITS * TIECAP];
__device__ int      g_cand[BATCH * CAND];
__device__ float4   g_sbox[BATCH * CAND];
__device__ float4   g_snb [BATCH * CAND];
__device__ float    g_sarea[BATCH * CAND];
__device__ float    g_sscore[BATCH * CAND];
__device__ int      g_slvl[BATCH * CAND];
__device__ uint4    g_mask4[(size_t)BATCH * CAND * MROW4];   // 16 MB
                    // upper triangle only (w >= row/32); lower stays 0 forever

__device__ __forceinline__ unsigned fkey(float f) {
    unsigned u = __float_as_uint(f);
    return (u & 0x80000000u) ? ~u : (u | 0x80000000u);
}
__device__ __forceinline__ float fkey_inv(unsigned u) {
    return (u & 0x80000000u) ? __uint_as_float(u & 0x7fffffffu)
                             : __uint_as_float(~u);
}
__device__ __forceinline__ unsigned long long shfl_xor_u64(unsigned long long v, int j) {
    unsigned lo = (unsigned)v, hi = (unsigned)(v >> 32);
    lo = __shfl_xor_sync(0xffffffffu, lo, j);
    hi = __shfl_xor_sync(0xffffffffu, hi, j);
    return ((unsigned long long)hi << 32) | lo;
}

// ---------------- K0: 12-bit smem histogram + fused prep (last block) ------
__global__ void histcoarse_kernel(const float* __restrict__ lg0,
                                  const float* __restrict__ lg1) {
    int unit = blockIdx.x / HS_HIST;
    int slice = blockIdx.x % HS_HIST;
    int b = unit >> 1, lvl = unit & 1;
    const float* lg = lvl ? (lg1 + (size_t)b * M1) : (lg0 + (size_t)b * M0);
    int M4 = (lvl ? M1 : M0) >> 2;
    const float4* lg4 = (const float4*)lg;
    int t = threadIdx.x;

    __shared__ unsigned sh[NB12];           // 16 KB
    for (int i = t; i < NB12; i += 512) sh[i] = 0u;
    __syncthreads();

    int chunk = (M4 + HS_HIST - 1) / HS_HIST;
    int s = slice * chunk;
    int e = s + chunk; if (e > M4) e = M4;
    for (int i = s + t; i < e; i += 512) {
        float4 v = lg4[i];
        atomicAdd(&sh[fkey(v.x) >> 20], 1u);
        atomicAdd(&sh[fkey(v.y) >> 20], 1u);
        atomicAdd(&sh[fkey(v.z) >> 20], 1u);
        atomicAdd(&sh[fkey(v.w) >> 20], 1u);
    }
    __syncthreads();
    unsigned* H = g_hist + unit * NB12;
    for (int i = t; i < NB12; i += 512)
        if (sh[i]) atomicAdd(&H[i], sh[i]);

    // ---- last-block election: fused prep ----
    __threadfence();
    __shared__ int isLast;
    if (t == 0) isLast = (atomicAdd(&g_histDone[unit], 1) == HS_HIST - 1);
    __syncthreads();
    if (!isLast) return;

    __shared__ unsigned chunkSum[512];
    unsigned cs = 0;
    #pragma unroll
    for (int j = 0; j < 8; ++j) cs += H[t * 8 + j];
    chunkSum[t] = cs;
    __syncthreads();
    if (t == 0) {
        unsigned cum = 0; int bsel = 0;
        for (int tt = 511; tt >= 0; --tt) {
            if (cum + chunkSum[tt] >= KSEL) {
                for (int j = 7; j >= 0; --j) {
                    unsigned c = H[tt * 8 + j];
                    if (cum + c >= KSEL) { bsel = tt * 8 + j; break; }
                    cum += c;
                }
                break;
            }
            cum += chunkSum[tt];
        }
        g_T12[unit] = (unsigned)bsel;
        g_cnt[unit] = 0;
        g_tieCnt[unit] = 0;
        g_histDone[unit] = 0;               // reset for next replay
    }
    __syncthreads();
    for (int i = t; i < NB12; i += 512) H[i] = 0u;   // re-zero for next replay
}

// ---------------- K1: chip-wide compaction (slot order irrelevant) ---------
__global__ void compact_kernel(const float* __restrict__ lg0,
                               const float* __restrict__ lg1) {
    int unit = blockIdx.x / HS_HIST;
    int slice = blockIdx.x % HS_HIST;
    int b = unit >> 1, lvl = unit & 1;
    const float* lg = lvl ? (lg1 + (size_t)b * M1) : (lg0 + (size_t)b * M0);
    int M4 = (lvl ? M1 : M0) >> 2;
    const float4* lg4 = (const float4*)lg;
    int t = threadIdx.x, lane = t & 31;
    unsigned T12 = g_T12[unit];
    int base = b * CAND + lvl * KSEL;

    int chunk = (M4 + HS_HIST - 1) / HS_HIST;
    int s = slice * chunk;
    int e = s + chunk; if (e > M4) e = M4;
    int iters = (e - s + 511) >> 9;         // padded: full-warp ballots safe

    for (int it = 0; it < iters; ++it) {
        int i = s + it * 512 + t;
        bool inb = (i < e);
        float4 v = inb ? lg4[i] : make_float4(0.f, 0.f, 0.f, 0.f);
        int ib = i * 4;
        unsigned uu[4] = { fkey(v.x), fkey(v.y), fkey(v.z), fkey(v.w) };
        #pragma unroll
        for (int c = 0; c < 4; ++c) {
            unsigned h = uu[c] >> 20;
            bool gt = inb && (h > T12);
            unsigned bal = __ballot_sync(0xffffffffu, gt);
            if (bal) {
                int leader = __ffs(bal) - 1;
                int rank = __popc(bal & ((1u << lane) - 1u));
                int bslot = 0;
                if (lane == leader) bslot = atomicAdd(&g_cnt[unit], __popc(bal));
                bslot = __shfl_sync(0xffffffffu, bslot, leader);
                if (gt) g_cand[base + bslot + rank] = (lvl << 18) | (ib + c);
            }
            bool tie = inb && (h == T12);
            if (tie) {
                int sl = atomicAdd(&g_tieCnt[unit], 1);
                if (sl < TIECAP)
                    g_tie[unit * TIECAP + sl] =
                        ((unsigned long long)uu[c] << 32) |
                        (unsigned)(~(unsigned)(ib + c));
            }
        }
    }
}

// ---------------- K2: rank ties (chip-wide: 14 slices per unit) ------------
__global__ void tierank_kernel() {
    int unit = blockIdx.x / TSLICE;
    int slice = blockIdx.x % TSLICE;
    int b = unit >> 1, lvl = unit & 1;
    int t = threadIdx.x;
    int n_gt = g_cnt[unit];
    int kRem = KSEL - n_gt;
    int n = g_tieCnt[unit]; if (n > TIECAP) n = TIECAP;
    int base = b * CAND + lvl * KSEL;

    __shared__ unsigned long long tk[TIECAP];   // 32 KB
    for (int i = t; i < n; i += 1024) tk[i] = g_tie[unit * TIECAP + i];
    __syncthreads();

    int chunk = (n + TSLICE - 1) / TSLICE;
    int s = slice * chunk;
    int e = s + chunk; if (e > n) e = n;
    for (int idx_e = s + t; idx_e < e; idx_e += 1024) {
        unsigned long long k = tk[idx_e];
        int r = 0;
        for (int c = 0; c < n; ++c) r += (tk[c] > k);
        if (r < kRem) {
            int idx = (int)(~(unsigned)k);
            g_cand[base + n_gt + r] = (lvl << 18) | idx;
        }
    }
}

// ---------------- K3: per-image hybrid bitonic sort + decode ---------------
__global__ void sortdecode_kernel(const float* __restrict__ lg0, const float* __restrict__ dl0,
                                  const float* __restrict__ lg1, const float* __restrict__ dl1,
                                  const float* __restrict__ an0, const float* __restrict__ an1) {
    int b = blockIdx.x, t = threadIdx.x;
    int lane = t & 31, warp = t >> 5;
    __shared__ unsigned long long key[4096];

    for (int i = t; i < 4096; i += 1024) {
        if (i < CAND) {
            int p = g_cand[b * CAND + i];
            int lvl = p >> 18, idx = p & 0x3ffff;
            float sc = lvl ? lg1[(size_t)b * M1 + idx] : lg0[(size_t)b * M0 + idx];
            key[i] = ((unsigned long long)fkey(sc) << 32) | (unsigned)(~(unsigned)p);
        } else key[i] = 0ull;
    }
    __syncthreads();

    // stage A: k = 2..32 fully in-register
    for (int blk = warp; blk < 128; blk += 32) {
        unsigned long long v = key[blk * 32 + lane];
        #pragma unroll
        for (int k = 2; k <= 16; k <<= 1) {
            bool desc = ((lane & k) == 0);
            #pragma unroll
            for (int j = k >> 1; j > 0; j >>= 1) {
                unsigned long long o = shfl_xor_u64(v, j);
                bool lower = (lane & j) == 0;
                bool takeMax = (lower == desc);
                v = takeMax ? (v > o ? v : o) : (v < o ? v : o);
            }
        }
        {
            bool desc = ((blk & 1) == 0);
            #pragma unroll
            for (int j = 16; j > 0; j >>= 1) {
                unsigned long long o = shfl_xor_u64(v, j);
                bool lower = (lane & j) == 0;
                bool takeMax = (lower == desc);
                v = takeMax ? (v > o ? v : o) : (v < o ? v : o);
            }
        }
        key[blk * 32 + lane] = v;
    }
    __syncthreads();

    // stage B: k = 64..4096; smem for j>=32, registers for j<=16
    for (int k = 64; k <= 4096; k <<= 1) {
        for (int j = k >> 1; j >= 32; j >>= 1) {
            for (int e = t; e < 4096; e += 1024) {
                int ix = e ^ j;
                if (ix > e) {
                    unsigned long long a = key[e], bb = key[ix];
                    bool swp = ((e & k) == 0) ? (a < bb) : (a > bb);
                    if (swp) { key[e] = bb; key[ix] = a; }
                }
            }
            __syncthreads();
        }
        for (int blk = warp; blk < 128; blk += 32) {
            unsigned long long v = key[blk * 32 + lane];
            bool desc = (((blk * 32) & k) == 0);
            #pragma unroll
            for (int j = 16; j > 0; j >>= 1) {
                unsigned long long o = shfl_xor_u64(v, j);
                bool lower = (lane & j) == 0;
                bool takeMax = (lower == desc);
                v = takeMax ? (v > o ? v : o) : (v < o ? v : o);
            }
            key[blk * 32 + lane] = v;
        }
        __syncthreads();
    }

    // decode in sorted order (strict per-op rounding, matches XLA)
    for (int i = t; i < CAND; i += 1024) {
        unsigned long long k = key[i];
        unsigned p = ~((unsigned)k);
        int lvl = (int)(p >> 18), idx = (int)(p & 0x3ffffu);
        float score = fkey_inv((unsigned)(k >> 32));

        const float* dl = lvl ? (dl1 + ((size_t)b * M1 + idx) * 4)
                              : (dl0 + ((size_t)b * M0 + idx) * 4);
        const float* an = (lvl ? an1 : an0) + (size_t)idx * 4;
        float4 a = *(const float4*)an;
        float4 d = *(const float4*)dl;

        float w  = __fsub_rn(a.z, a.x);
        float h  = __fsub_rn(a.w, a.y);
        float cx = __fadd_rn(a.x, __fmul_rn(0.5f, w));
        float cy = __fadd_rn(a.y, __fmul_rn(0.5f, h));
        float dw = fminf(d.z, SCALE_CLAMPF);
        float dh = fminf(d.w, SCALE_CLAMPF);
        float pcx = __fadd_rn(__fmul_rn(d.x, w), cx);
        float pcy = __fadd_rn(__fmul_rn(d.y, h), cy);
        float pw  = __fmul_rn(expf(dw), w);
        float ph  = __fmul_rn(expf(dh), h);
        float hpw = __fmul_rn(0.5f, pw);
        float hph = __fmul_rn(0.5f, ph);
        float x1 = __fsub_rn(pcx, hpw);
        float y1 = __fsub_rn(pcy, hph);
        float x2 = __fadd_rn(pcx, hpw);
        float y2 = __fadd_rn(pcy, hph);
        x1 = fminf(fmaxf(x1, 0.f), IMG_Wf);
        x2 = fminf(fmaxf(x2, 0.f), IMG_Wf);
        y1 = fminf(fmaxf(y1, 0.f), IMG_Hf);
        y2 = fminf(fmaxf(y2, 0.f), IMG_Hf);

        int gi = b * CAND + i;
        g_sbox[gi] = make_float4(x1, y1, x2, y2);
        float off = lvl ? LVL_OFF : 0.f;
        float nx1 = __fadd_rn(x1, off), ny1 = __fadd_rn(y1, off);
        float nx2 = __fadd_rn(x2, off), ny2 = __fadd_rn(y2, off);
        g_snb[gi]   = make_float4(nx1, ny1, nx2, ny2);
        g_sarea[gi] = __fmul_rn(__fsub_rn(nx2, nx1), __fsub_rn(ny2, ny1));
        g_sscore[gi] = score;
        g_slvl[gi]  = lvl;
    }
}

// ---------------- K4: UPPER-TRIANGLE suppression bitmask -------------------
// Fast path: iou>0.7 <=> inter > (7/17)(areaJ+areaN). Border lanes fall back
// to the exact reference formula per-lane (predicated; no warp vote).
__global__ void __launch_bounds__(256, 4) mask_kernel() {
    int blk = blockIdx.x;
    int b = blk / 250, rg = blk % 250;
    int t = threadIdx.x, wi = t >> 5, lane = t & 31;
    int rowBase = rg * MB_ROWS;
    int wStart = rowBase >> 5;             // min diagonal word in this block

    __shared__ float4 rb[MB_ROWS];
    __shared__ float  ra[MB_ROWS];         // exact areas (for fallback)
    __shared__ float  rs[MB_ROWS];         // scaled areas (fast path)
    if (t < MB_ROWS) {
        rb[t] = g_snb[b * CAND + rowBase + t];
        float av = g_sarea[b * CAND + rowBase + t];
        ra[t] = av;
        rs[t] = IOU_C * av;
    }
    __syncthreads();

    unsigned* gm = (unsigned*)g_mask4;
    for (int w = wStart + wi; w < NWORD; w += 8) {
        int col = b * CAND + w * 32 + lane;
        float4 nb = g_snb[col];
        float  na = g_sarea[col];
        float  ns = IOU_C * na;
        size_t obase = (size_t)(b * CAND + rowBase) * MROW + w;
        #pragma unroll 4
        for (int r = 0; r < MB_ROWS; ++r) {
            float4 jb = rb[r];
            float ix1 = fmaxf(jb.x, nb.x), iy1 = fmaxf(jb.y, nb.y);
            float ix2 = fminf(jb.z, nb.z), iy2 = fminf(jb.w, nb.w);
            float iw = fmaxf(__fsub_rn(ix2, ix1), 0.f);
            float ih = fmaxf(__fsub_rn(iy2, iy1), 0.f);
            float inter = __fmul_rn(iw, ih);
            float rhs = rs[r] + ns;
            bool over = inter > rhs;
            if (fabsf(inter - rhs) < (1e-3f * rhs + 1e-5f)) {   // rare, per-lane
                float denom = fmaxf(__fsub_rn(__fadd_rn(ra[r], na), inter), 1e-6f);
                over = (__fdiv_rn(inter, denom) > NMS_T);
            }
            unsigned bits = __ballot_sync(0xffffffffu, over);
            if (lane == 0) gm[obase + (size_t)r * MROW] = bits;
        }
    }
}

// ---------------- K5: single-warp forward scan, batched row ORs ------------
__global__ void scan_kernel(float* __restrict__ out) {
    int b = blockIdx.x;
    int t = threadIdx.x, warp = t >> 5, lane = t & 31;
    __shared__ int selList[POSTK];
    __shared__ int sh_sel, sh_padi;

    const unsigned* mw = (const unsigned*)g_mask4 + (size_t)b * CAND * MROW;

    if (warp == 0) {
        unsigned m0 = 0, m1 = 0, m2 = 0, m3 = 0;   // lane L owns words 4L..4L+3
        int sel = 0;
        unsigned diag = mw[(size_t)lane * MROW];   // word 0 diag
        for (int w = 0; w < NWORD && sel < POSTK; ++w) {
            unsigned diagNext = 0;
            if (w + 1 < NWORD)
                diagNext = mw[(size_t)((w + 1) * 32 + lane) * MROW + (w + 1)];

            unsigned mv = (w & 3) == 0 ? m0 : (w & 3) == 1 ? m1 : (w & 3) == 2 ? m2 : m3;
            unsigned cur = __shfl_sync(0xffffffffu, mv, w >> 2);
            unsigned alive = ~cur;
            unsigned acc = 0;
            while (alive && sel < POSTK) {
                int bit = __ffs(alive) - 1;
                acc |= (1u << bit);
                if (lane == 0) selList[sel] = w * 32 + bit;
                sel++;
                unsigned rw = __shfl_sync(0xffffffffu, diag, bit);
                alive &= ~rw;
                alive &= ~(1u << bit);
            }
            // OR accepted rows: 8 independent LDG.128 per batch (MLP=8).
            while (acc) {
                int idx[8];
                idx[0] = w * 32 + (__ffs(acc) - 1); acc &= acc - 1;
                #pragma unroll
                for (int u = 1; u < 8; ++u) {
                    if (acc) { idx[u] = w * 32 + (__ffs(acc) - 1); acc &= acc - 1; }
                    else idx[u] = idx[0];
                }
                uint4 rv[8];
                #pragma unroll
                for (int u = 0; u < 8; ++u)
                    rv[u] = *(const uint4*)(mw + (size_t)idx[u] * MROW + lane * 4);
                #pragma unroll
                for (int u = 0; u < 8; ++u) {
                    m0 |= rv[u].x; m1 |= rv[u].y; m2 |= rv[u].z; m3 |= rv[u].w;
                }
            }
            diag = diagNext;
        }
        if (lane == 0) sh_sel = sel;
    }
    if (t == 0) {
        int p = 0;
        while (g_slvl[b * CAND + p] != 0) ++p;   // concat position 0 = 1st lvl-0
        sh_padi = p;
    }
    __syncthreads();

    // -------- parallel output epilogue (all 256 threads) --------
    int sel = sh_sel;
    int padi = sh_padi;
    for (int r = t; r < POSTK; r += blockDim.x) {
        int src = (r < sel) ? selList[r] : padi;
        float4 bx = g_sbox[b * CAND + src];
        float sc = g_sscore[b * CAND + src];
        float* o = out + ((size_t)b * POSTK + r) * 5;
        o[0] = bx.x; o[1] = bx.y; o[2] = bx.z; o[3] = bx.w; o[4] = sc;
    }
}

// ---------------------------------------------------------------------------
extern "C" void kernel_launch(void* const* d_in, const int* in_sizes, int n_in,
                              void* d_out, int out_size) {
    const float* lg0 = (const float*)d_in[0];
    const float* dl0 = (const float*)d_in[1];
    const float* lg1 = (const float*)d_in[2];
    const float* dl1 = (const float*)d_in[3];
    const float* an0 = (const float*)d_in[4];
    const float* an1 = (const float*)d_in[5];
    float* out = (float*)d_out;

    histcoarse_kernel<<<NUNITS * HS_HIST, 512>>>(lg0, lg1);
    compact_kernel<<<NUNITS * HS_HIST, 512>>>(lg0, lg1);
    tierank_kernel<<<NUNITS * TSLICE, 1024>>>();
    sortdecode_kernel<<<BATCH, 1024>>>(lg0, dl0, lg1, dl1, an0, an1);
    mask_kernel<<<BATCH * 250, 256>>>();
    scan_kernel<<<BATCH, 256>>>(out);
}